// round 11
// baseline (speedup 1.0000x reference)
#include <cuda_runtime.h>
#include <math.h>
#include <stdint.h>

// ============================ scratch ============================
__device__ float  g_Weff[400 * 400];
__device__ float  g_beff[400];
__device__ float  g_attn[16383 * 400];
__device__ float  g_G[(size_t)16384 * 5504];           // GRU preacts; also weight fp32 temp
__device__ float  g_flatF[(size_t)16384 * 1600];
__device__ float  g_x1F[(size_t)16384 * 3648];
__device__ float  g_x3F[(size_t)16384 * 1920];
__device__ float  g_x5F[(size_t)16384 * 1920];

__device__ int8_t g_flatH8[(size_t)16384 * 1600];
__device__ int8_t g_flatL8[(size_t)16384 * 1600];
__device__ float  g_sFlat[16384];
__device__ int8_t g_x1H8[(size_t)16384 * 3648];
__device__ int8_t g_x1L8[(size_t)16384 * 3648];
__device__ float  g_sX1[16384];
__device__ int8_t g_x3H8[(size_t)16384 * 1920];
__device__ int8_t g_x3L8[(size_t)16384 * 1920];
__device__ float  g_sX3[16384];
__device__ int8_t g_x5H8[(size_t)16384 * 1920];
__device__ int8_t g_x5L8[(size_t)16384 * 1920];
__device__ float  g_sX5[16384];

__device__ int8_t g_WgfH8[(size_t)5504 * 1600];
__device__ int8_t g_WgfL8[(size_t)5504 * 1600];
__device__ float  g_sWgf[5504];
__device__ int8_t g_WgbH8[(size_t)5504 * 1600];
__device__ int8_t g_WgbL8[(size_t)5504 * 1600];
__device__ float  g_sWgb[5504];
__device__ int8_t g_Wd2H8[(size_t)1920 * 3648];
__device__ int8_t g_Wd2L8[(size_t)1920 * 3648];
__device__ float  g_sWd2[1920];
__device__ int8_t g_Wd4H8[(size_t)1920 * 1920];
__device__ int8_t g_Wd4L8[(size_t)1920 * 1920];
__device__ float  g_sWd4[1920];
__device__ int8_t g_Wo1H8[(size_t)192 * 3648];
__device__ int8_t g_Wo1L8[(size_t)192 * 3648];
__device__ float  g_sWo1[192];
__device__ int8_t g_Wo2H8[(size_t)192 * 1920];
__device__ int8_t g_Wo2L8[(size_t)192 * 1920];
__device__ float  g_sWo2[192];
__device__ int8_t g_Wo3H8[(size_t)192 * 1920];
__device__ int8_t g_Wo3L8[(size_t)192 * 1920];
__device__ float  g_sWo3[192];

// ============================ ptx helpers ============================
__device__ __forceinline__ uint32_t s2u(const void* p) {
    uint32_t a;
    asm("{ .reg .u64 t; cvta.to.shared.u64 t, %1; cvt.u32.u64 %0, t; }" : "=r"(a) : "l"(p));
    return a;
}
__device__ __forceinline__ void ldm_x4(uint32_t* r, uint32_t addr) {
    asm volatile("ldmatrix.sync.aligned.m8n8.x4.shared.b16 {%0,%1,%2,%3}, [%4];"
                 : "=r"(r[0]), "=r"(r[1]), "=r"(r[2]), "=r"(r[3]) : "r"(addr));
}
__device__ __forceinline__ void imma16832(int32_t* c, const uint32_t* a, const uint32_t* b) {
    asm volatile("mma.sync.aligned.m16n8k32.row.col.s32.s8.s8.s32 "
                 "{%0,%1,%2,%3}, {%4,%5,%6,%7}, {%8,%9}, {%0,%1,%2,%3};"
                 : "+r"(c[0]), "+r"(c[1]), "+r"(c[2]), "+r"(c[3])
                 : "r"(a[0]), "r"(a[1]), "r"(a[2]), "r"(a[3]), "r"(b[0]), "r"(b[1]));
}
__device__ __forceinline__ void cp16(uint32_t saddr, const void* g) {
    asm volatile("cp.async.cg.shared.global [%0], [%1], 16;" :: "r"(saddr), "l"(g) : "memory");
}

// ============================ IMMA GEMM ============================
// C[16384, 64*gridX] = A[16384, K] @ Bt[Npad, K]^T in 15-bit fixed point.
// A/B: int8 hi/lo digit pairs + per-row scales. acc = 16384*hh + 128*(hl+lh).
// EPI 0: C = v + bias(col<biasN), fp32.
// EPI 1: OF = elu(v + bias(col<biasN)), fp32.
// EPI 2: col<Nvalid: C = v + bias  (addC=0)  or  C += v  (addC=1).
#define PITCH_B 80                    // bytes per smem row (64 int8 + 16 pad)
#define A_T (128 * PITCH_B)           // 10240
#define B_T (64 * PITCH_B)            // 5120
#define STG (2 * A_T + 2 * B_T)       // 30720

template<int EPI>
__global__ __launch_bounds__(256, 2)
void imma_gemm(const int8_t* __restrict__ AH, const int8_t* __restrict__ AL, int lda,
               const float* __restrict__ sA,
               const int8_t* __restrict__ BH, const int8_t* __restrict__ BL, int ldb,
               const float* __restrict__ sB,
               int K, float* __restrict__ C, int ldc,
               const float* __restrict__ bias, int biasN,
               float* __restrict__ OF, int ldo, int Nvalid, int addC)
{
    extern __shared__ char smem[];
    const uint32_t su = s2u(smem);
    const int tid = threadIdx.x;
    const int lane = tid & 31;
    const int wid = tid >> 5;
    const int warp_m = wid & 1;         // 2 x 64 rows
    const int warp_n = wid >> 1;        // 4 x 16 cols
    const size_t rowA = (size_t)blockIdx.y * 128;
    const size_t rowB = (size_t)blockIdx.x * 64;
    const int NCH = K / 64;

    const int aRow0 = tid >> 2, aRow1 = (tid + 256) >> 2;
    const int cOff = (tid & 3) * 16;
    const int bRowL = tid >> 2;

    auto issue = [&](int ch, int s) {
        const int k0 = ch * 64;
        uint32_t st = su + s * STG;
        uint32_t dA0 = st + aRow0 * PITCH_B + cOff;
        uint32_t dA1 = st + aRow1 * PITCH_B + cOff;
        size_t ga0 = (rowA + aRow0) * (size_t)lda + k0 + cOff;
        size_t ga1 = (rowA + aRow1) * (size_t)lda + k0 + cOff;
        cp16(dA0,        AH + ga0);  cp16(dA1,        AH + ga1);
        cp16(dA0 + A_T,  AL + ga0);  cp16(dA1 + A_T,  AL + ga1);
        uint32_t dB = st + 2 * A_T + bRowL * PITCH_B + cOff;
        size_t gb = (rowB + bRowL) * (size_t)ldb + k0 + cOff;
        cp16(dB,        BH + gb);
        cp16(dB + B_T,  BL + gb);
        asm volatile("cp.async.commit_group;" ::: "memory");
    };

    int32_t acc1[4][2][4], acc2[4][2][4];
#pragma unroll
    for (int i = 0; i < 4; i++)
#pragma unroll
        for (int j = 0; j < 2; j++)
#pragma unroll
            for (int k = 0; k < 4; k++) { acc1[i][j][k] = 0; acc2[i][j][k] = 0; }

    issue(0, 0);

    const int aLRow = lane & 15, aKH = lane >> 4;
    const int bRow = (lane & 7) + ((lane >> 4) << 3);
    const int bKH = (lane >> 3) & 1;

    for (int ch = 0; ch < NCH; ch++) {
        const int s = ch & 1;
        asm volatile("cp.async.wait_group 0;" ::: "memory");
        __syncthreads();
        if (ch + 1 < NCH) issue(ch + 1, s ^ 1);

        const uint32_t st = su + s * STG;
#pragma unroll
        for (int s2 = 0; s2 < 2; s2++) {              // two k32 steps per 64-K chunk
            const int colB = s2 * 32;
            // B fragments (hi & lo): one x4 covers both nf (16 rows)
            uint32_t bH[2][2], bL[2][2];
            {
                uint32_t ad = st + 2 * A_T + (warp_n * 16 + bRow) * PITCH_B + colB + bKH * 16;
                uint32_t t[4];
                ldm_x4(t, ad);
                bH[0][0] = t[0]; bH[0][1] = t[1]; bH[1][0] = t[2]; bH[1][1] = t[3];
                ldm_x4(t, ad + B_T);
                bL[0][0] = t[0]; bL[0][1] = t[1]; bL[1][0] = t[2]; bL[1][1] = t[3];
            }
            uint32_t a[4][4];
#pragma unroll
            for (int mf = 0; mf < 4; mf++) {
                uint32_t ad = st + (warp_m * 64 + mf * 16 + aLRow) * PITCH_B + colB + aKH * 16;
                ldm_x4(a[mf], ad);
            }
#pragma unroll
            for (int mf = 0; mf < 4; mf++)
#pragma unroll
                for (int nf = 0; nf < 2; nf++)
                    imma16832(acc1[mf][nf], a[mf], bH[nf]);   // hi*hi
#pragma unroll
            for (int mf = 0; mf < 4; mf++)
#pragma unroll
                for (int nf = 0; nf < 2; nf++)
                    imma16832(acc2[mf][nf], a[mf], bL[nf]);   // hi*lo
#pragma unroll
            for (int mf = 0; mf < 4; mf++) {
                uint32_t ad = st + A_T + (warp_m * 64 + mf * 16 + aLRow) * PITCH_B + colB + aKH * 16;
                ldm_x4(a[mf], ad);
            }
#pragma unroll
            for (int mf = 0; mf < 4; mf++)
#pragma unroll
                for (int nf = 0; nf < 2; nf++)
                    imma16832(acc2[mf][nf], a[mf], bH[nf]);   // lo*hi
        }
    }

    // ---------------- epilogue ----------------
    const int rBase = (int)rowA + warp_m * 64 + (lane >> 2);
    const int cBase = (int)rowB + warp_n * 16 + (lane & 3) * 2;
#pragma unroll
    for (int mf = 0; mf < 4; mf++) {
#pragma unroll
        for (int half = 0; half < 2; half++) {
            const size_t r = rBase + mf * 16 + half * 8;
            const float sa = sA[r];
#pragma unroll
            for (int nf = 0; nf < 2; nf++) {
                const int col = cBase + nf * 8;
                float v0 = sa * sB[col + 0] *
                           (16384.f * (float)acc1[mf][nf][half * 2 + 0] + 128.f * (float)acc2[mf][nf][half * 2 + 0]);
                float v1 = sa * sB[col + 1] *
                           (16384.f * (float)acc1[mf][nf][half * 2 + 1] + 128.f * (float)acc2[mf][nf][half * 2 + 1]);
                if (EPI == 0) {
                    if (col + 0 < biasN) v0 += bias[col + 0];
                    if (col + 1 < biasN) v1 += bias[col + 1];
                    *reinterpret_cast<float2*>(C + r * (size_t)ldc + col) = make_float2(v0, v1);
                } else if (EPI == 1) {
                    if (col + 0 < biasN) v0 += bias[col + 0];
                    if (col + 1 < biasN) v1 += bias[col + 1];
                    v0 = v0 > 0.f ? v0 : expm1f(v0);
                    v1 = v1 > 0.f ? v1 : expm1f(v1);
                    *reinterpret_cast<float2*>(OF + r * (size_t)ldo + col) = make_float2(v0, v1);
                } else {
                    if (col + 0 < Nvalid) {
                        float o = addC ? (C[r * (size_t)ldc + col + 0] + v0) : (v0 + bias[col + 0]);
                        C[r * (size_t)ldc + col + 0] = o;
                    }
                    if (col + 1 < Nvalid) {
                        float o = addC ? (C[r * (size_t)ldc + col + 1] + v1) : (v1 + bias[col + 1]);
                        C[r * (size_t)ldc + col + 1] = o;
                    }
                }
            }
        }
    }
}

// ============================ quantization ============================
__device__ __forceinline__ float blockReduceMax(float v, float* sh)
{
#pragma unroll
    for (int o = 16; o > 0; o >>= 1) v = fmaxf(v, __shfl_xor_sync(0xffffffffu, v, o));
    int lane = threadIdx.x & 31, warp = threadIdx.x >> 5;
    if (lane == 0) sh[warp] = v;
    __syncthreads();
    if (warp == 0) {
        float r = (lane < 8) ? sh[lane] : 0.f;
#pragma unroll
        for (int o = 4; o > 0; o >>= 1) r = fmaxf(r, __shfl_xor_sync(0xffffffffu, r, o));
        if (lane == 0) sh[0] = r;
    }
    __syncthreads();
    float r = sh[0];
    __syncthreads();
    return r;
}

// One block per row: scale = max|row|/16256; a15 -> hi (int8), lo (int8).
__global__ __launch_bounds__(256)
void rowquant_kernel(const float* __restrict__ src, int lds, int Ksrc, int ldq,
                     int8_t* __restrict__ H, int8_t* __restrict__ L, float* __restrict__ scale)
{
    __shared__ float red[32];
    const int r = blockIdx.x;
    const int t = threadIdx.x;
    const float* s = src + (size_t)r * lds;
    float m = 0.f;
    for (int k = t; k < Ksrc; k += 256) m = fmaxf(m, fabsf(s[k]));
    m = blockReduceMax(m, red);
    float mx = fmaxf(m, 1e-20f);
    if (t == 0) scale[r] = mx / 16256.f;
    const float inv = 16256.f / mx;
    for (int k = t; k < ldq; k += 256) {
        float v = (k < Ksrc) ? s[k] : 0.f;
        int a15 = __float2int_rn(v * inv);
        int hi = (a15 + 64) >> 7;
        int lo = a15 - (hi << 7);
        H[(size_t)r * ldq + k] = (int8_t)hi;
        L[(size_t)r * ldq + k] = (int8_t)lo;
    }
}

// Transpose with zero-fill: Bt[n, k] = B[k, n]; grid covers padded (Kpad/32, Npad/32).
__global__ void convT_kernel(const float* __restrict__ B, int Ksrc, int Nsrc, int ldbsrc,
                             float* __restrict__ Bt, int ldbt)
{
    __shared__ float t[32][33];
    int k0 = blockIdx.x * 32, n0 = blockIdx.y * 32;
    int tx = threadIdx.x, ty = threadIdx.y;
#pragma unroll
    for (int i = 0; i < 4; i++) {
        int k = k0 + ty + i * 8, n = n0 + tx;
        t[ty + i * 8][tx] = (k < Ksrc && n < Nsrc) ? B[(size_t)k * ldbsrc + n] : 0.f;
    }
    __syncthreads();
#pragma unroll
    for (int i = 0; i < 4; i++) {
        int n = n0 + ty + i * 8, k = k0 + tx;
        Bt[(size_t)n * ldbt + k] = t[tx][ty + i * 8];
    }
}

// ============================ SIMT SGEMM (front-end only) ============================
#define BM 128
#define BN 128
#define BK 8
__global__ __launch_bounds__(256, 2)
void sgemm_kernel(const float* __restrict__ A, const float* __restrict__ B,
                  float* __restrict__ C, const float* __restrict__ bias,
                  int M, int N, int K, int lda, int ldb, int ldc, int flags, int kChunk)
{
    __shared__ float As[BK][BM];
    __shared__ float Bs[BK][BN];
    const int tid = threadIdx.x;
    const int tx = tid & 15, ty = tid >> 4;
    const int rowBase = blockIdx.y * BM, colBase = blockIdx.x * BN;
    const int kStart = blockIdx.z * kChunk;
    const int kEnd = min(kStart + kChunk, K);
    float acc[8][8];
#pragma unroll
    for (int i = 0; i < 8; i++)
#pragma unroll
        for (int j = 0; j < 8; j++) acc[i][j] = 0.f;
    const int aRow = tid >> 1, aCol = (tid & 1) * 4, gARow = rowBase + aRow;
    const int bRow = tid >> 5, bCol = (tid & 31) * 4, gBCol = colBase + bCol;
    for (int k0 = kStart; k0 < kEnd; k0 += BK) {
        float4 av = make_float4(0.f, 0.f, 0.f, 0.f);
        if (gARow < M) av = *reinterpret_cast<const float4*>(A + (size_t)gARow * lda + k0 + aCol);
        As[aCol + 0][aRow] = av.x; As[aCol + 1][aRow] = av.y;
        As[aCol + 2][aRow] = av.z; As[aCol + 3][aRow] = av.w;
        float4 bv = make_float4(0.f, 0.f, 0.f, 0.f);
        if (gBCol < N) bv = *reinterpret_cast<const float4*>(B + (size_t)(k0 + bRow) * ldb + gBCol);
        *reinterpret_cast<float4*>(&Bs[bRow][bCol]) = bv;
        __syncthreads();
#pragma unroll
        for (int kk = 0; kk < BK; kk++) {
            float4 a0 = *reinterpret_cast<const float4*>(&As[kk][ty * 8]);
            float4 a1 = *reinterpret_cast<const float4*>(&As[kk][ty * 8 + 4]);
            float4 b0 = *reinterpret_cast<const float4*>(&Bs[kk][tx * 8]);
            float4 b1 = *reinterpret_cast<const float4*>(&Bs[kk][tx * 8 + 4]);
            float a[8] = {a0.x, a0.y, a0.z, a0.w, a1.x, a1.y, a1.z, a1.w};
            float b[8] = {b0.x, b0.y, b0.z, b0.w, b1.x, b1.y, b1.z, b1.w};
#pragma unroll
            for (int i = 0; i < 8; i++)
#pragma unroll
                for (int j = 0; j < 8; j++) acc[i][j] = fmaf(a[i], b[j], acc[i][j]);
        }
        __syncthreads();
    }
#pragma unroll
    for (int i = 0; i < 8; i++) {
        int row = rowBase + ty * 8 + i;
        if (row >= M) continue;
#pragma unroll
        for (int j = 0; j < 8; j++) {
            int col = colBase + tx * 8 + j;
            if (col >= N) continue;
            float v = acc[i][j];
            size_t off = (size_t)row * ldc + col;
            if (flags & 4) atomicAdd(&C[off], v);
            else { if (bias) v += bias[col]; C[off] = v; }
        }
    }
}

// ============================ small helpers ============================
__global__ void zero_weff_kernel()
{
    int i = blockIdx.x * 256 + threadIdx.x;
    if (i < 400 * 400) g_Weff[i] = 0.f;
}
__global__ void beff_kernel(const float* __restrict__ bv, const float* __restrict__ Wo,
                            const float* __restrict__ bo)
{
    int d = blockIdx.x * 256 + threadIdx.x;
    if (d >= 400) return;
    float acc = bo[d];
    for (int j = 0; j < 6400; j++) acc = fmaf(bv[j], Wo[(size_t)j * 400 + d], acc);
    g_beff[d] = acc;
}
__global__ void build_flatF(const float* __restrict__ x)
{
    int idx = blockIdx.x * 256 + threadIdx.x;
    const int total = 16384 * 1200;
    if (idx < total) {
        int b = idx / 1200, c = idx - b * 1200;
        g_flatF[(size_t)b * 1600 + c] = x[idx];
    } else if (idx < total + 400) {
        int d = idx - total;
        g_flatF[1200 + d] = x[800 + d];
    }
}

__device__ __forceinline__ float blockReduceSum(float v, float* sh)
{
#pragma unroll
    for (int o = 16; o > 0; o >>= 1) v += __shfl_xor_sync(0xffffffffu, v, o);
    int lane = threadIdx.x & 31, warp = threadIdx.x >> 5;
    if (lane == 0) sh[warp] = v;
    __syncthreads();
    if (warp == 0) {
        float r = (lane < 8) ? sh[lane] : 0.f;
#pragma unroll
        for (int o = 4; o > 0; o >>= 1) r += __shfl_xor_sync(0xffffffffu, r, o);
        if (lane == 0) sh[0] = r;
    }
    __syncthreads();
    float r = sh[0];
    __syncthreads();
    return r;
}

__global__ __launch_bounds__(256)
void frontend_kernel(const float* __restrict__ x,
                     const float* __restrict__ ln1g, const float* __restrict__ ln1b,
                     const float* __restrict__ w1,  const float* __restrict__ fb1,
                     const float* __restrict__ w2,  const float* __restrict__ fb2,
                     const float* __restrict__ ln2g, const float* __restrict__ ln2b)
{
    int b = blockIdx.x;
    const float* xe = x + (size_t)(b + 1) * 1200 + 800;
    const float* at = g_attn + (size_t)b * 400;
    __shared__ float red[32];
    int t = threadIdx.x;
    float sv[2], o1[2], s2v[2];
    int dIdx[2], cnt = 0;
    float sum = 0.f, sq = 0.f;
    for (int d = t; d < 400; d += 256) {
        float v = xe[d] + at[d];
        sv[cnt] = v; dIdx[cnt] = d; cnt++;
        sum += v; sq += v * v;
    }
    sum = blockReduceSum(sum, red);
    sq  = blockReduceSum(sq, red);
    float mean = sum * (1.f / 400.f);
    float var  = sq * (1.f / 400.f) - mean * mean;
    float rstd = rsqrtf(var + 1e-6f);
    float t0 = 0.f, t1 = 0.f;
    for (int i = 0; i < cnt; i++) {
        int d = dIdx[i];
        float o = (sv[i] - mean) * rstd * ln1g[d] + ln1b[d];
        o1[i] = o;
        t0 = fmaf(o, w1[2 * d], t0);
        t1 = fmaf(o, w1[2 * d + 1], t1);
    }
    t0 = blockReduceSum(t0, red);
    t1 = blockReduceSum(t1, red);
    t0 = fmaxf(t0 + fb1[0], 0.f);
    t1 = fmaxf(t1 + fb1[1], 0.f);
    sum = 0.f; sq = 0.f;
    for (int i = 0; i < cnt; i++) {
        int d = dIdx[i];
        float v = o1[i] + t0 * w2[d] + t1 * w2[400 + d] + fb2[d];
        s2v[i] = v; sum += v; sq += v * v;
    }
    sum = blockReduceSum(sum, red);
    sq  = blockReduceSum(sq, red);
    mean = sum * (1.f / 400.f);
    var  = sq * (1.f / 400.f) - mean * mean;
    rstd = rsqrtf(var + 1e-6f);
    size_t base = (size_t)(b + 1) * 1600 + 1200;
    for (int i = 0; i < cnt; i++) {
        int d = dIdx[i];
        g_flatF[base + d] = (s2v[i] - mean) * rstd * ln2g[d] + ln2b[d];
    }
}

__global__ void gru_elem_kernel(const float* __restrict__ Brow1, int colOff)
{
    int idx = blockIdx.x * 256 + threadIdx.x;
    if (idx >= 16384 * 1800) return;
    int b = idx / 1800, j = idx - b * 1800;
    const float* g = g_G + (size_t)b * 5504;
    float z = 1.f / (1.f + expf(-(g[j] + Brow1[j])));
    float r = 1.f / (1.f + expf(-(g[1800 + j] + Brow1[1800 + j])));
    float hv = g[3600 + j] + r * Brow1[3600 + j];
    float hh = (hv > 0.f) ? hv : expm1f(hv);
    g_x1F[(size_t)b * 3648 + colOff + j] = (1.f - z) * hh;
}

// ============================ host ============================
static void imma_launch(int epi, int nxt, const int8_t* AH, const int8_t* AL, int lda, const float* sA,
                        const int8_t* BH, const int8_t* BL, int ldb, const float* sB,
                        int K, float* C, int ldc, const float* bias, int biasN,
                        float* OF, int ldo, int Nvalid, int addC)
{
    dim3 grid(nxt, 128);
    if (epi == 0)
        imma_gemm<0><<<grid, 256, 2 * STG>>>(AH, AL, lda, sA, BH, BL, ldb, sB, K, C, ldc, bias, biasN, OF, ldo, Nvalid, addC);
    else if (epi == 1)
        imma_gemm<1><<<grid, 256, 2 * STG>>>(AH, AL, lda, sA, BH, BL, ldb, sB, K, C, ldc, bias, biasN, OF, ldo, Nvalid, addC);
    else
        imma_gemm<2><<<grid, 256, 2 * STG>>>(AH, AL, lda, sA, BH, BL, ldb, sB, K, C, ldc, bias, biasN, OF, ldo, Nvalid, addC);
}

extern "C" void kernel_launch(void* const* d_in, const int* in_sizes, int n_in,
                              void* d_out, int out_size)
{
    (void)n_in; (void)out_size;
    const float* x  = (const float*)d_in[0];
    const float* Wv = (const float*)d_in[5];
    const float* bv = (const float*)d_in[6];
    const float* Wo = (const float*)d_in[7];
    const float* bo = (const float*)d_in[8];

    bool sigOrder = (in_sizes[10] == 400);
    const float *ln1g, *ln1b, *w1, *fb1, *w2, *fb2, *ln2g, *ln2b;
    const float *gfk, *gfb, *gbk, *gbb, *d2w, *d2b, *d4w, *d4b, *ow, *ob;
    if (sigOrder) {
        ln1g = (const float*)d_in[9];  ln1b = (const float*)d_in[10];
        w1   = (const float*)d_in[11]; fb1  = (const float*)d_in[12];
        w2   = (const float*)d_in[13]; fb2  = (const float*)d_in[14];
        ln2g = (const float*)d_in[15]; ln2b = (const float*)d_in[16];
        gfk  = (const float*)d_in[17]; gfb  = (const float*)d_in[19];
        gbk  = (const float*)d_in[20]; gbb  = (const float*)d_in[22];
        d2w  = (const float*)d_in[23]; d2b  = (const float*)d_in[24];
        d4w  = (const float*)d_in[25]; d4b  = (const float*)d_in[26];
        ow   = (const float*)d_in[27]; ob   = (const float*)d_in[28];
    } else {
        ln1b = (const float*)d_in[9];
        w1   = (const float*)d_in[10]; fb1  = (const float*)d_in[11];
        w2   = (const float*)d_in[12]; fb2  = (const float*)d_in[13];
        ln2b = (const float*)d_in[14];
        gfk  = (const float*)d_in[15]; gfb  = (const float*)d_in[17];
        gbk  = (const float*)d_in[18]; gbb  = (const float*)d_in[20];
        d2w  = (const float*)d_in[21]; d2b  = (const float*)d_in[22];
        d4w  = (const float*)d_in[23]; d4b  = (const float*)d_in[24];
        ow   = (const float*)d_in[25]; ob   = (const float*)d_in[26];
        ln1g = (const float*)d_in[27]; ln2g = (const float*)d_in[28];
    }

    float *pWeff, *pbeff, *pattn, *pG, *pflatF, *px1F, *px3F, *px5F;
    cudaGetSymbolAddress((void**)&pWeff, g_Weff);
    cudaGetSymbolAddress((void**)&pbeff, g_beff);
    cudaGetSymbolAddress((void**)&pattn, g_attn);
    cudaGetSymbolAddress((void**)&pG, g_G);
    cudaGetSymbolAddress((void**)&pflatF, g_flatF);
    cudaGetSymbolAddress((void**)&px1F, g_x1F);
    cudaGetSymbolAddress((void**)&px3F, g_x3F);
    cudaGetSymbolAddress((void**)&px5F, g_x5F);

    int8_t *pflatH8, *pflatL8, *px1H8, *px1L8, *px3H8, *px3L8, *px5H8, *px5L8;
    float *psFlat, *psX1, *psX3, *psX5;
    cudaGetSymbolAddress((void**)&pflatH8, g_flatH8);
    cudaGetSymbolAddress((void**)&pflatL8, g_flatL8);
    cudaGetSymbolAddress((void**)&psFlat, g_sFlat);
    cudaGetSymbolAddress((void**)&px1H8, g_x1H8);
    cudaGetSymbolAddress((void**)&px1L8, g_x1L8);
    cudaGetSymbolAddress((void**)&psX1, g_sX1);
    cudaGetSymbolAddress((void**)&px3H8, g_x3H8);
    cudaGetSymbolAddress((void**)&px3L8, g_x3L8);
    cudaGetSymbolAddress((void**)&psX3, g_sX3);
    cudaGetSymbolAddress((void**)&px5H8, g_x5H8);
    cudaGetSymbolAddress((void**)&px5L8, g_x5L8);
    cudaGetSymbolAddress((void**)&psX5, g_sX5);

    int8_t *pWgfH8, *pWgfL8, *pWgbH8, *pWgbL8, *pWd2H8, *pWd2L8, *pWd4H8, *pWd4L8;
    int8_t *pWo1H8, *pWo1L8, *pWo2H8, *pWo2L8, *pWo3H8, *pWo3L8;
    float *psWgf, *psWgb, *psWd2, *psWd4, *psWo1, *psWo2, *psWo3;
    cudaGetSymbolAddress((void**)&pWgfH8, g_WgfH8);
    cudaGetSymbolAddress((void**)&pWgfL8, g_WgfL8);
    cudaGetSymbolAddress((void**)&psWgf, g_sWgf);
    cudaGetSymbolAddress((void**)&pWgbH8, g_WgbH8);
    cudaGetSymbolAddress((void**)&pWgbL8, g_WgbL8);
    cudaGetSymbolAddress((void**)&psWgb, g_sWgb);
    cudaGetSymbolAddress((void**)&pWd2H8, g_Wd2H8);
    cudaGetSymbolAddress((void**)&pWd2L8, g_Wd2L8);
    cudaGetSymbolAddress((void**)&psWd2, g_sWd2);
    cudaGetSymbolAddress((void**)&pWd4H8, g_Wd4H8);
    cudaGetSymbolAddress((void**)&pWd4L8, g_Wd4L8);
    cudaGetSymbolAddress((void**)&psWd4, g_sWd4);
    cudaGetSymbolAddress((void**)&pWo1H8, g_Wo1H8);
    cudaGetSymbolAddress((void**)&pWo1L8, g_Wo1L8);
    cudaGetSymbolAddress((void**)&psWo1, g_sWo1);
    cudaGetSymbolAddress((void**)&pWo2H8, g_Wo2H8);
    cudaGetSymbolAddress((void**)&pWo2L8, g_Wo2L8);
    cudaGetSymbolAddress((void**)&psWo2, g_sWo2);
    cudaGetSymbolAddress((void**)&pWo3H8, g_Wo3H8);
    cudaGetSymbolAddress((void**)&pWo3L8, g_Wo3L8);
    cudaGetSymbolAddress((void**)&psWo3, g_sWo3);
    float* out = (float*)d_out;

    cudaFuncSetAttribute(imma_gemm<0>, cudaFuncAttributeMaxDynamicSharedMemorySize, 2 * STG);
    cudaFuncSetAttribute(imma_gemm<1>, cudaFuncAttributeMaxDynamicSharedMemorySize, 2 * STG);
    cudaFuncSetAttribute(imma_gemm<2>, cudaFuncAttributeMaxDynamicSharedMemorySize, 2 * STG);

    // --- front-end (SIMT fp32) ---
    zero_weff_kernel<<<(400 * 400 + 255) / 256, 256>>>();
    { dim3 g(4, 4, 8); sgemm_kernel<<<g, 256>>>(Wv, Wo, pWeff, nullptr, 400, 400, 6400, 6400, 400, 400, 4, 800); }
    beff_kernel<<<2, 256>>>(bv, Wo, bo);
    { dim3 g(4, 128, 1); sgemm_kernel<<<g, 256>>>(x + 2000, pWeff, pattn, pbeff, 16383, 400, 400, 1200, 400, 400, 0, 400); }
    build_flatF<<<(16384 * 1200 + 400 + 255) / 256, 256>>>(x);
    frontend_kernel<<<16383, 256>>>(x, ln1g, ln1b, w1, fb1, w2, fb2, ln2g, ln2b);
    rowquant_kernel<<<16384, 256>>>(pflatF, 1600, 1600, 1600, pflatH8, pflatL8, psFlat);

    // --- weight conversion: transpose (zero-fill) into g_G temp, then rowquant ---
    float* wtmp = pG;   // g_G used as scratch BEFORE the GRU GEMMs
    { dim3 g(50, 172);  convT_kernel<<<g, dim3(32, 8)>>>(gfk, 1600, 5400, 5400, wtmp, 1600);
      rowquant_kernel<<<5504, 256>>>(wtmp, 1600, 1600, 1600, pWgfH8, pWgfL8, psWgf); }
    { dim3 g(50, 172);  convT_kernel<<<g, dim3(32, 8)>>>(gbk, 1600, 5400, 5400, wtmp, 1600);
      rowquant_kernel<<<5504, 256>>>(wtmp, 1600, 1600, 1600, pWgbH8, pWgbL8, psWgb); }
    { dim3 g(114, 60);  convT_kernel<<<g, dim3(32, 8)>>>(d2w, 3600, 1800, 1800, wtmp, 3648);
      rowquant_kernel<<<1920, 256>>>(wtmp, 3648, 3648, 3648, pWd2H8, pWd2L8, psWd2); }
    { dim3 g(60, 60);   convT_kernel<<<g, dim3(32, 8)>>>(d4w, 1800, 1800, 1800, wtmp, 1920);
      rowquant_kernel<<<1920, 256>>>(wtmp, 1920, 1920, 1920, pWd4H8, pWd4L8, psWd4); }
    { dim3 g(114, 6);   convT_kernel<<<g, dim3(32, 8)>>>(ow,              3600, 140, 140, wtmp, 3648);
      rowquant_kernel<<<192, 256>>>(wtmp, 3648, 3648, 3648, pWo1H8, pWo1L8, psWo1); }
    { dim3 g(60, 6);    convT_kernel<<<g, dim3(32, 8)>>>(ow + 3600 * 140, 1800, 140, 140, wtmp, 1920);
      rowquant_kernel<<<192, 256>>>(wtmp, 1920, 1920, 1920, pWo2H8, pWo2L8, psWo2); }
    { dim3 g(60, 6);    convT_kernel<<<g, dim3(32, 8)>>>(ow + 5400 * 140, 1800, 140, 140, wtmp, 1920);
      rowquant_kernel<<<192, 256>>>(wtmp, 1920, 1920, 1920, pWo3H8, pWo3L8, psWo3); }

    // --- tensor GEMMs (int8 IMMA, 3-digit fixed point) ---
    // GRU forward
    imma_launch(0, 86, pflatH8, pflatL8, 1600, psFlat, pWgfH8, pWgfL8, 1600, psWgf,
                1600, pG, 5504, gfb, 5400, nullptr, 0, 5504, 0);
    gru_elem_kernel<<<(16384 * 1800 + 255) / 256, 256>>>(gfb + 5400, 0);
    // GRU backward
    imma_launch(0, 86, pflatH8, pflatL8, 1600, psFlat, pWgbH8, pWgbL8, 1600, psWgb,
                1600, pG, 5504, gbb, 5400, nullptr, 0, 5504, 0);
    gru_elem_kernel<<<(16384 * 1800 + 255) / 256, 256>>>(gbb + 5400, 1800);
    rowquant_kernel<<<16384, 256>>>(px1F, 3648, 3600, 3648, px1H8, px1L8, psX1);
    // x3 = elu(x1 @ d2w + b)
    imma_launch(1, 30, px1H8, px1L8, 3648, psX1, pWd2H8, pWd2L8, 3648, psWd2,
                3648, nullptr, 0, d2b, 1800, px3F, 1920, 1920, 0);
    rowquant_kernel<<<16384, 256>>>(px3F, 1920, 1920, 1920, px3H8, px3L8, psX3);
    // x5 = elu(x3 @ d4w + b)
    imma_launch(1, 30, px3H8, px3L8, 1920, psX3, pWd4H8, pWd4L8, 1920, psWd4,
                1920, nullptr, 0, d4b, 1800, px5F, 1920, 1920, 0);
    rowquant_kernel<<<16384, 256>>>(px5F, 1920, 1920, 1920, px5H8, px5L8, psX5);
    // out = x1@W1 + x3@W2 + x5@W3 + ob
    imma_launch(2, 3, px1H8, px1L8, 3648, psX1, pWo1H8, pWo1L8, 3648, psWo1,
                3648, out, 140, ob, 140, nullptr, 0, 140, 0);
    imma_launch(2, 3, px3H8, px3L8, 1920, psX3, pWo2H8, pWo2L8, 1920, psWo2,
                1920, out, 140, ob, 140, nullptr, 0, 140, 1);
    imma_launch(2, 3, px5H8, px5L8, 1920, psX5, pWo3H8, pWo3L8, 1920, psWo3,
                1920, out, 140, ob, 140, nullptr, 0, 140, 1);
}

// round 12
// speedup vs baseline: 2.1875x; 2.1875x over previous
#include <cuda_runtime.h>
#include <cuda_fp16.h>
#include <math.h>
#include <stdint.h>

typedef __half f16;

// ============================ scratch ============================
__device__ float g_Weff[400 * 400];
__device__ float g_beff[400];
__device__ float g_attn[16383 * 400];
__device__ float g_G[(size_t)16384 * 5504];
__device__ f16   g_flatA[(size_t)16384 * 1600];
__device__ f16   g_x1A[(size_t)16384 * 3648];
__device__ f16   g_x3A[(size_t)16384 * 1920];
__device__ f16   g_x5A[(size_t)16384 * 1920];
__device__ f16   g_BgfH[(size_t)5504 * 1600];
__device__ f16   g_BgfL[(size_t)5504 * 1600];
__device__ f16   g_BgbH[(size_t)5504 * 1600];
__device__ f16   g_BgbL[(size_t)5504 * 1600];
__device__ f16   g_Bd2H[(size_t)1920 * 3648];
__device__ f16   g_Bd2L[(size_t)1920 * 3648];
__device__ f16   g_Bd4H[(size_t)1920 * 1920];
__device__ f16   g_Bd4L[(size_t)1920 * 1920];
__device__ f16   g_BoH[(size_t)256 * 7488];
__device__ f16   g_BoL[(size_t)256 * 7488];

// ============================ ptx helpers (plain sm_103-legal) ============================
__device__ __forceinline__ uint32_t s2u(const void* p) {
    uint32_t a;
    asm("{ .reg .u64 t; cvta.to.shared.u64 t, %1; cvt.u32.u64 %0, t; }" : "=r"(a) : "l"(p));
    return a;
}
__device__ __forceinline__ void ldm_x4(uint32_t* r, uint32_t addr) {
    asm volatile("ldmatrix.sync.aligned.m8n8.x4.shared.b16 {%0,%1,%2,%3}, [%4];"
                 : "=r"(r[0]), "=r"(r[1]), "=r"(r[2]), "=r"(r[3]) : "r"(addr));
}
__device__ __forceinline__ void mma16816(float* c, const uint32_t* a, const uint32_t* b) {
    asm volatile("mma.sync.aligned.m16n8k16.row.col.f32.f16.f16.f32 "
                 "{%0,%1,%2,%3}, {%4,%5,%6,%7}, {%8,%9}, {%0,%1,%2,%3};"
                 : "+f"(c[0]), "+f"(c[1]), "+f"(c[2]), "+f"(c[3])
                 : "r"(a[0]), "r"(a[1]), "r"(a[2]), "r"(a[3]), "r"(b[0]), "r"(b[1]));
}
__device__ __forceinline__ void cp16(uint32_t saddr, const void* g) {
    asm volatile("cp.async.cg.shared.global [%0], [%1], 16;" :: "r"(saddr), "l"(g) : "memory");
}

// ============================ HMMA GEMM (fp16, weight-split 2-term) ============================
// C[16384, 128*gridX] = concat(A1|A2|A3)[16384, Ktot] @ Bt[Npad, Ktot]^T
// A: single fp16. B: fp16 hi/lo digit pair. acc += A*Bhi + A*Blo (fp32 accum).
// EPI 0: C = acc + bias(col<biasN). EPI 1: elu(acc+bias) -> fp16 OA.
// EPI 2: C[col<Nvalid] = acc + bias.
#define PITCH 40                   // f16 elems per smem row (80B; conflict-free)
#define TILE_B (128 * PITCH * 2)   // 10240
#define STAGE_B (3 * TILE_B)       // 30720 (A, Bhi, Blo)

template<int EPI>
__global__ __launch_bounds__(256, 2)
void hmma_gemm(const f16* __restrict__ A1, const f16* __restrict__ A2, const f16* __restrict__ A3,
               int lda1, int lda2, int lda3, int kb1, int kb2, int Ktot,
               const f16* __restrict__ BH, const f16* __restrict__ BL, int ldb,
               float* __restrict__ C, int ldc,
               const float* __restrict__ bias, int biasN,
               f16* __restrict__ OA, int ldo, int Nvalid)
{
    extern __shared__ char smem[];
    const uint32_t su = s2u(smem);
    const int tid = threadIdx.x;
    const int lane = tid & 31;
    const int wid = tid >> 5;
    const int warp_m = wid & 1;       // 2 x 64 rows
    const int warp_n = wid >> 1;      // 4 x 32 cols
    const size_t rowA = (size_t)blockIdx.y * 128;
    const size_t rowB = (size_t)blockIdx.x * 128;
    const int NCH = Ktot / 32;

    const int ldRow0 = tid >> 2, ldC0 = (tid & 3);
    const int ldRow1 = (tid + 256) >> 2, ldC1 = ldC0;

    auto issue = [&](int ch, int s) {
        const int k0 = ch * 32;
        const f16* pA; int kl; size_t lda;
        if (k0 < kb1)      { pA = A1; kl = k0;       lda = (size_t)lda1; }
        else if (k0 < kb2) { pA = A2; kl = k0 - kb1; lda = (size_t)lda2; }
        else               { pA = A3; kl = k0 - kb2; lda = (size_t)lda3; }
        uint32_t st = su + s * STAGE_B;
        uint32_t d0 = st + ldRow0 * (PITCH * 2) + ldC0 * 16;
        uint32_t d1 = st + ldRow1 * (PITCH * 2) + ldC1 * 16;
        size_t a0 = (rowA + ldRow0) * lda + kl + ldC0 * 8;
        size_t a1 = (rowA + ldRow1) * lda + kl + ldC1 * 8;
        size_t b0 = (rowB + ldRow0) * (size_t)ldb + k0 + ldC0 * 8;
        size_t b1 = (rowB + ldRow1) * (size_t)ldb + k0 + ldC1 * 8;
        cp16(d0,              pA + a0);  cp16(d1,              pA + a1);
        cp16(d0 + TILE_B,     BH + b0);  cp16(d1 + TILE_B,     BH + b1);
        cp16(d0 + 2 * TILE_B, BL + b0);  cp16(d1 + 2 * TILE_B, BL + b1);
        asm volatile("cp.async.commit_group;" ::: "memory");
    };

    float acc[4][4][4];
#pragma unroll
    for (int i = 0; i < 4; i++)
#pragma unroll
        for (int j = 0; j < 4; j++)
#pragma unroll
            for (int k = 0; k < 4; k++) acc[i][j][k] = 0.f;

    issue(0, 0);

    const int aLRow = lane & 15, aKH = lane >> 4;
    const int bRow = (lane & 7) + ((lane >> 4) << 3);
    const int bKH = (lane >> 3) & 1;

    for (int ch = 0; ch < NCH; ch++) {
        const int s = ch & 1;
        asm volatile("cp.async.wait_group 0;" ::: "memory");
        __syncthreads();
        if (ch + 1 < NCH) issue(ch + 1, s ^ 1);

        const uint32_t st = su + s * STAGE_B;
#pragma unroll
        for (int kk2 = 0; kk2 < 2; kk2++) {
            const int kcol = kk2 * 16;
            uint32_t bH[4][2], bL[4][2];
#pragma unroll
            for (int np = 0; np < 2; np++) {
                uint32_t ad = st + TILE_B + (warp_n * 32 + np * 16 + bRow) * (PITCH * 2) + (kcol + 8 * bKH) * 2;
                uint32_t t[4];
                ldm_x4(t, ad);
                bH[np * 2][0] = t[0]; bH[np * 2][1] = t[1];
                bH[np * 2 + 1][0] = t[2]; bH[np * 2 + 1][1] = t[3];
                ldm_x4(t, ad + TILE_B);
                bL[np * 2][0] = t[0]; bL[np * 2][1] = t[1];
                bL[np * 2 + 1][0] = t[2]; bL[np * 2 + 1][1] = t[3];
            }
            uint32_t a[4][4];
#pragma unroll
            for (int mf = 0; mf < 4; mf++) {
                uint32_t ad = st + (warp_m * 64 + mf * 16 + aLRow) * (PITCH * 2) + (kcol + 8 * aKH) * 2;
                ldm_x4(a[mf], ad);
            }
#pragma unroll
            for (int mf = 0; mf < 4; mf++)
#pragma unroll
                for (int nf = 0; nf < 4; nf++)
                    mma16816(acc[mf][nf], a[mf], bH[nf]);     // A*Bhi x16
#pragma unroll
            for (int mf = 0; mf < 4; mf++)
#pragma unroll
                for (int nf = 0; nf < 4; nf++)
                    mma16816(acc[mf][nf], a[mf], bL[nf]);     // A*Blo x16
        }
    }

    // ---------------- epilogue ----------------
    const int rBase = (int)rowA + warp_m * 64 + (lane >> 2);
    const int cBase = (int)rowB + warp_n * 32 + (lane & 3) * 2;
#pragma unroll
    for (int mf = 0; mf < 4; mf++) {
#pragma unroll
        for (int half = 0; half < 2; half++) {
            const size_t r = rBase + mf * 16 + half * 8;
#pragma unroll
            for (int nf = 0; nf < 4; nf++) {
                const int col = cBase + nf * 8;
                float v0 = acc[mf][nf][half * 2 + 0];
                float v1 = acc[mf][nf][half * 2 + 1];
                if (EPI == 0) {
                    if (col + 0 < biasN) v0 += bias[col + 0];
                    if (col + 1 < biasN) v1 += bias[col + 1];
                    *reinterpret_cast<float2*>(C + r * (size_t)ldc + col) = make_float2(v0, v1);
                } else if (EPI == 1) {
                    if (col + 0 < biasN) v0 += bias[col + 0];
                    if (col + 1 < biasN) v1 += bias[col + 1];
                    v0 = v0 > 0.f ? v0 : expm1f(v0);
                    v1 = v1 > 0.f ? v1 : expm1f(v1);
                    __half2 p = __floats2half2_rn(v0, v1);
                    *reinterpret_cast<__half2*>(OA + r * (size_t)ldo + col) = p;
                } else {
                    if (col + 0 < Nvalid) C[r * (size_t)ldc + col + 0] = v0 + bias[col + 0];
                    if (col + 1 < Nvalid) C[r * (size_t)ldc + col + 1] = v1 + bias[col + 1];
                }
            }
        }
    }
}

// ============================ weight transpose + fp16 hi/lo split ============================
__global__ void convB_kernel(const float* __restrict__ B, int Ksrc, int Nsrc, int ldbsrc,
                             f16* __restrict__ BtH, f16* __restrict__ BtL, int ldbt, int kOff)
{
    __shared__ float t[32][33];
    int k0 = blockIdx.x * 32, n0 = blockIdx.y * 32;
    int tx = threadIdx.x, ty = threadIdx.y;
#pragma unroll
    for (int i = 0; i < 4; i++) {
        int k = k0 + ty + i * 8, n = n0 + tx;
        t[ty + i * 8][tx] = (k < Ksrc && n < Nsrc) ? B[(size_t)k * ldbsrc + n] : 0.f;
    }
    __syncthreads();
#pragma unroll
    for (int i = 0; i < 4; i++) {
        int n = n0 + ty + i * 8, k = k0 + tx;
        float v = t[tx][ty + i * 8];
        f16 h = __float2half(v);
        size_t o = (size_t)n * ldbt + kOff + k;
        BtH[o] = h;
        BtL[o] = __float2half(v - __half2float(h));
    }
}

// ============================ SIMT SGEMM (front-end only) ============================
#define BM 128
#define BN 128
#define BK 8
__global__ __launch_bounds__(256, 2)
void sgemm_kernel(const float* __restrict__ A, const float* __restrict__ B,
                  float* __restrict__ C, const float* __restrict__ bias,
                  int M, int N, int K, int lda, int ldb, int ldc, int flags, int kChunk)
{
    __shared__ float As[BK][BM];
    __shared__ float Bs[BK][BN];
    const int tid = threadIdx.x;
    const int tx = tid & 15, ty = tid >> 4;
    const int rowBase = blockIdx.y * BM, colBase = blockIdx.x * BN;
    const int kStart = blockIdx.z * kChunk;
    const int kEnd = min(kStart + kChunk, K);
    float acc[8][8];
#pragma unroll
    for (int i = 0; i < 8; i++)
#pragma unroll
        for (int j = 0; j < 8; j++) acc[i][j] = 0.f;
    const int aRow = tid >> 1, aCol = (tid & 1) * 4, gARow = rowBase + aRow;
    const int bRow = tid >> 5, bCol = (tid & 31) * 4, gBCol = colBase + bCol;
    for (int k0 = kStart; k0 < kEnd; k0 += BK) {
        float4 av = make_float4(0.f, 0.f, 0.f, 0.f);
        if (gARow < M) av = *reinterpret_cast<const float4*>(A + (size_t)gARow * lda + k0 + aCol);
        As[aCol + 0][aRow] = av.x; As[aCol + 1][aRow] = av.y;
        As[aCol + 2][aRow] = av.z; As[aCol + 3][aRow] = av.w;
        float4 bv = make_float4(0.f, 0.f, 0.f, 0.f);
        if (gBCol < N) bv = *reinterpret_cast<const float4*>(B + (size_t)(k0 + bRow) * ldb + gBCol);
        *reinterpret_cast<float4*>(&Bs[bRow][bCol]) = bv;
        __syncthreads();
#pragma unroll
        for (int kk = 0; kk < BK; kk++) {
            float4 a0 = *reinterpret_cast<const float4*>(&As[kk][ty * 8]);
            float4 a1 = *reinterpret_cast<const float4*>(&As[kk][ty * 8 + 4]);
            float4 b0 = *reinterpret_cast<const float4*>(&Bs[kk][tx * 8]);
            float4 b1 = *reinterpret_cast<const float4*>(&Bs[kk][tx * 8 + 4]);
            float a[8] = {a0.x, a0.y, a0.z, a0.w, a1.x, a1.y, a1.z, a1.w};
            float b[8] = {b0.x, b0.y, b0.z, b0.w, b1.x, b1.y, b1.z, b1.w};
#pragma unroll
            for (int i = 0; i < 8; i++)
#pragma unroll
                for (int j = 0; j < 8; j++) acc[i][j] = fmaf(a[i], b[j], acc[i][j]);
        }
        __syncthreads();
    }
#pragma unroll
    for (int i = 0; i < 8; i++) {
        int row = rowBase + ty * 8 + i;
        if (row >= M) continue;
#pragma unroll
        for (int j = 0; j < 8; j++) {
            int col = colBase + tx * 8 + j;
            if (col >= N) continue;
            float v = acc[i][j];
            size_t off = (size_t)row * ldc + col;
            if (flags & 4) atomicAdd(&C[off], v);
            else { if (bias) v += bias[col]; C[off] = v; }
        }
    }
}

// ============================ small helpers ============================
__global__ void zero_weff_kernel()
{
    int i = blockIdx.x * 256 + threadIdx.x;
    if (i < 400 * 400) g_Weff[i] = 0.f;
}
__global__ void beff_kernel(const float* __restrict__ bv, const float* __restrict__ Wo,
                            const float* __restrict__ bo)
{
    int d = blockIdx.x * 256 + threadIdx.x;
    if (d >= 400) return;
    float acc = bo[d];
    for (int j = 0; j < 6400; j++) acc = fmaf(bv[j], Wo[(size_t)j * 400 + d], acc);
    g_beff[d] = acc;
}
__global__ void build_flat_f16(const float* __restrict__ x)
{
    int idx = blockIdx.x * 256 + threadIdx.x;
    const int total = 16384 * 1200;
    float v; size_t dst;
    if (idx < total) {
        int b = idx / 1200, c = idx - b * 1200;
        v = x[idx]; dst = (size_t)b * 1600 + c;
    } else if (idx < total + 400) {
        int d = idx - total;
        v = x[800 + d]; dst = 1200 + d;
    } else return;
    g_flatA[dst] = __float2half(v);
}
__global__ void pad_x1_kernel()
{
    int i = blockIdx.x * 256 + threadIdx.x;
    if (i >= 16384 * 48) return;
    int b = i / 48, c = 3600 + i % 48;
    g_x1A[(size_t)b * 3648 + c] = __float2half(0.f);
}

__device__ __forceinline__ float blockReduceSum(float v, float* sh)
{
#pragma unroll
    for (int o = 16; o > 0; o >>= 1) v += __shfl_xor_sync(0xffffffffu, v, o);
    int lane = threadIdx.x & 31, warp = threadIdx.x >> 5;
    if (lane == 0) sh[warp] = v;
    __syncthreads();
    if (warp == 0) {
        float r = (lane < 8) ? sh[lane] : 0.f;
#pragma unroll
        for (int o = 4; o > 0; o >>= 1) r += __shfl_xor_sync(0xffffffffu, r, o);
        if (lane == 0) sh[0] = r;
    }
    __syncthreads();
    float r = sh[0];
    __syncthreads();
    return r;
}

__global__ __launch_bounds__(256)
void frontend_kernel(const float* __restrict__ x,
                     const float* __restrict__ ln1g, const float* __restrict__ ln1b,
                     const float* __restrict__ w1,  const float* __restrict__ fb1,
                     const float* __restrict__ w2,  const float* __restrict__ fb2,
                     const float* __restrict__ ln2g, const float* __restrict__ ln2b)
{
    int b = blockIdx.x;
    const float* xe = x + (size_t)(b + 1) * 1200 + 800;
    const float* at = g_attn + (size_t)b * 400;
    __shared__ float red[32];
    int t = threadIdx.x;
    float sv[2], o1[2], s2v[2];
    int dIdx[2], cnt = 0;
    float sum = 0.f, sq = 0.f;
    for (int d = t; d < 400; d += 256) {
        float v = xe[d] + at[d];
        sv[cnt] = v; dIdx[cnt] = d; cnt++;
        sum += v; sq += v * v;
    }
    sum = blockReduceSum(sum, red);
    sq  = blockReduceSum(sq, red);
    float mean = sum * (1.f / 400.f);
    float var  = sq * (1.f / 400.f) - mean * mean;
    float rstd = rsqrtf(var + 1e-6f);
    float t0 = 0.f, t1 = 0.f;
    for (int i = 0; i < cnt; i++) {
        int d = dIdx[i];
        float o = (sv[i] - mean) * rstd * ln1g[d] + ln1b[d];
        o1[i] = o;
        t0 = fmaf(o, w1[2 * d], t0);
        t1 = fmaf(o, w1[2 * d + 1], t1);
    }
    t0 = blockReduceSum(t0, red);
    t1 = blockReduceSum(t1, red);
    t0 = fmaxf(t0 + fb1[0], 0.f);
    t1 = fmaxf(t1 + fb1[1], 0.f);
    sum = 0.f; sq = 0.f;
    for (int i = 0; i < cnt; i++) {
        int d = dIdx[i];
        float v = o1[i] + t0 * w2[d] + t1 * w2[400 + d] + fb2[d];
        s2v[i] = v; sum += v; sq += v * v;
    }
    sum = blockReduceSum(sum, red);
    sq  = blockReduceSum(sq, red);
    mean = sum * (1.f / 400.f);
    var  = sq * (1.f / 400.f) - mean * mean;
    rstd = rsqrtf(var + 1e-6f);
    size_t base = (size_t)(b + 1) * 1600 + 1200;
    for (int i = 0; i < cnt; i++) {
        int d = dIdx[i];
        g_flatA[base + d] = __float2half((s2v[i] - mean) * rstd * ln2g[d] + ln2b[d]);
    }
}

__global__ void gru_elem_kernel(const float* __restrict__ Brow1, int colOff)
{
    int idx = blockIdx.x * 256 + threadIdx.x;
    if (idx >= 16384 * 1800) return;
    int b = idx / 1800, j = idx - b * 1800;
    const float* g = g_G + (size_t)b * 5504;
    float z = 1.f / (1.f + expf(-(g[j] + Brow1[j])));
    float r = 1.f / (1.f + expf(-(g[1800 + j] + Brow1[1800 + j])));
    float hv = g[3600 + j] + r * Brow1[3600 + j];
    float hh = (hv > 0.f) ? hv : expm1f(hv);
    g_x1A[(size_t)b * 3648 + colOff + j] = __float2half((1.f - z) * hh);
}

// ============================ host ============================
#define HM_SMEM (2 * STAGE_B)   // 61440

static void hm_launch(int epi, int nTiles,
                      const f16* A1, const f16* A2, const f16* A3,
                      int lda1, int lda2, int lda3, int kb1, int kb2, int Ktot,
                      const f16* BH, const f16* BL, int ldb,
                      float* C, int ldc, const float* bias, int biasN,
                      f16* OA, int ldo, int Nvalid)
{
    dim3 grid(nTiles, 128);
    if (epi == 0)
        hmma_gemm<0><<<grid, 256, HM_SMEM>>>(A1, A2, A3, lda1, lda2, lda3, kb1, kb2, Ktot,
                                             BH, BL, ldb, C, ldc, bias, biasN, OA, ldo, Nvalid);
    else if (epi == 1)
        hmma_gemm<1><<<grid, 256, HM_SMEM>>>(A1, A2, A3, lda1, lda2, lda3, kb1, kb2, Ktot,
                                             BH, BL, ldb, C, ldc, bias, biasN, OA, ldo, Nvalid);
    else
        hmma_gemm<2><<<grid, 256, HM_SMEM>>>(A1, A2, A3, lda1, lda2, lda3, kb1, kb2, Ktot,
                                             BH, BL, ldb, C, ldc, bias, biasN, OA, ldo, Nvalid);
}

extern "C" void kernel_launch(void* const* d_in, const int* in_sizes, int n_in,
                              void* d_out, int out_size)
{
    (void)n_in; (void)out_size;
    const float* x  = (const float*)d_in[0];
    const float* Wv = (const float*)d_in[5];
    const float* bv = (const float*)d_in[6];
    const float* Wo = (const float*)d_in[7];
    const float* bo = (const float*)d_in[8];

    bool sigOrder = (in_sizes[10] == 400);
    const float *ln1g, *ln1b, *w1, *fb1, *w2, *fb2, *ln2g, *ln2b;
    const float *gfk, *gfb, *gbk, *gbb, *d2w, *d2b, *d4w, *d4b, *ow, *ob;
    if (sigOrder) {
        ln1g = (const float*)d_in[9];  ln1b = (const float*)d_in[10];
        w1   = (const float*)d_in[11]; fb1  = (const float*)d_in[12];
        w2   = (const float*)d_in[13]; fb2  = (const float*)d_in[14];
        ln2g = (const float*)d_in[15]; ln2b = (const float*)d_in[16];
        gfk  = (const float*)d_in[17]; gfb  = (const float*)d_in[19];
        gbk  = (const float*)d_in[20]; gbb  = (const float*)d_in[22];
        d2w  = (const float*)d_in[23]; d2b  = (const float*)d_in[24];
        d4w  = (const float*)d_in[25]; d4b  = (const float*)d_in[26];
        ow   = (const float*)d_in[27]; ob   = (const float*)d_in[28];
    } else {
        ln1b = (const float*)d_in[9];
        w1   = (const float*)d_in[10]; fb1  = (const float*)d_in[11];
        w2   = (const float*)d_in[12]; fb2  = (const float*)d_in[13];
        ln2b = (const float*)d_in[14];
        gfk  = (const float*)d_in[15]; gfb  = (const float*)d_in[17];
        gbk  = (const float*)d_in[18]; gbb  = (const float*)d_in[20];
        d2w  = (const float*)d_in[21]; d2b  = (const float*)d_in[22];
        d4w  = (const float*)d_in[23]; d4b  = (const float*)d_in[24];
        ow   = (const float*)d_in[25]; ob   = (const float*)d_in[26];
        ln1g = (const float*)d_in[27]; ln2g = (const float*)d_in[28];
    }

    float *pWeff, *pbeff, *pattn, *pG;
    f16 *pflatA, *px1A, *px3A, *px5A;
    f16 *pBgfH, *pBgfL, *pBgbH, *pBgbL, *pBd2H, *pBd2L, *pBd4H, *pBd4L, *pBoH, *pBoL;
    cudaGetSymbolAddress((void**)&pWeff, g_Weff);
    cudaGetSymbolAddress((void**)&pbeff, g_beff);
    cudaGetSymbolAddress((void**)&pattn, g_attn);
    cudaGetSymbolAddress((void**)&pG, g_G);
    cudaGetSymbolAddress((void**)&pflatA, g_flatA);
    cudaGetSymbolAddress((void**)&px1A, g_x1A);
    cudaGetSymbolAddress((void**)&px3A, g_x3A);
    cudaGetSymbolAddress((void**)&px5A, g_x5A);
    cudaGetSymbolAddress((void**)&pBgfH, g_BgfH);
    cudaGetSymbolAddress((void**)&pBgfL, g_BgfL);
    cudaGetSymbolAddress((void**)&pBgbH, g_BgbH);
    cudaGetSymbolAddress((void**)&pBgbL, g_BgbL);
    cudaGetSymbolAddress((void**)&pBd2H, g_Bd2H);
    cudaGetSymbolAddress((void**)&pBd2L, g_Bd2L);
    cudaGetSymbolAddress((void**)&pBd4H, g_Bd4H);
    cudaGetSymbolAddress((void**)&pBd4L, g_Bd4L);
    cudaGetSymbolAddress((void**)&pBoH, g_BoH);
    cudaGetSymbolAddress((void**)&pBoL, g_BoL);
    float* out = (float*)d_out;

    cudaFuncSetAttribute(hmma_gemm<0>, cudaFuncAttributeMaxDynamicSharedMemorySize, HM_SMEM);
    cudaFuncSetAttribute(hmma_gemm<1>, cudaFuncAttributeMaxDynamicSharedMemorySize, HM_SMEM);
    cudaFuncSetAttribute(hmma_gemm<2>, cudaFuncAttributeMaxDynamicSharedMemorySize, HM_SMEM);

    // --- front-end (SIMT fp32) ---
    zero_weff_kernel<<<(400 * 400 + 255) / 256, 256>>>();
    { dim3 g(4, 4, 8); sgemm_kernel<<<g, 256>>>(Wv, Wo, pWeff, nullptr, 400, 400, 6400, 6400, 400, 400, 4, 800); }
    beff_kernel<<<2, 256>>>(bv, Wo, bo);
    { dim3 g(4, 128, 1); sgemm_kernel<<<g, 256>>>(x + 2000, pWeff, pattn, pbeff, 16383, 400, 400, 1200, 400, 400, 0, 400); }
    build_flat_f16<<<(16384 * 1200 + 400 + 255) / 256, 256>>>(x);
    frontend_kernel<<<16383, 256>>>(x, ln1g, ln1b, w1, fb1, w2, fb2, ln2g, ln2b);

    // --- weight conversion (transpose + fp16 hi/lo split, padded) ---
    { dim3 g(1600 / 32, 5504 / 32); convB_kernel<<<g, dim3(32, 8)>>>(gfk, 1600, 5400, 5400, pBgfH, pBgfL, 1600, 0); }
    { dim3 g(1600 / 32, 5504 / 32); convB_kernel<<<g, dim3(32, 8)>>>(gbk, 1600, 5400, 5400, pBgbH, pBgbL, 1600, 0); }
    { dim3 g(3648 / 32, 1920 / 32); convB_kernel<<<g, dim3(32, 8)>>>(d2w, 3600, 1800, 1800, pBd2H, pBd2L, 3648, 0); }
    { dim3 g(1920 / 32, 1920 / 32); convB_kernel<<<g, dim3(32, 8)>>>(d4w, 1800, 1800, 1800, pBd4H, pBd4L, 1920, 0); }
    { dim3 g(3648 / 32, 256 / 32);  convB_kernel<<<g, dim3(32, 8)>>>(ow,              3600, 140, 140, pBoH, pBoL, 7488, 0); }
    { dim3 g(1920 / 32, 256 / 32);  convB_kernel<<<g, dim3(32, 8)>>>(ow + 3600 * 140, 1800, 140, 140, pBoH, pBoL, 7488, 3648); }
    { dim3 g(1920 / 32, 256 / 32);  convB_kernel<<<g, dim3(32, 8)>>>(ow + 5400 * 140, 1800, 140, 140, pBoH, pBoL, 7488, 5568); }
    pad_x1_kernel<<<(16384 * 48 + 255) / 256, 256>>>();

    // --- tensor-core GEMMs (mma.sync fp16, weight-split 2-term) ---
    hm_launch(0, 43, pflatA, pflatA, pflatA, 1600, 1600, 1600, 1600, 1600, 1600,
              pBgfH, pBgfL, 1600, pG, 5504, gfb, 5400, nullptr, 0, 5504);
    gru_elem_kernel<<<(16384 * 1800 + 255) / 256, 256>>>(gfb + 5400, 0);
    hm_launch(0, 43, pflatA, pflatA, pflatA, 1600, 1600, 1600, 1600, 1600, 1600,
              pBgbH, pBgbL, 1600, pG, 5504, gbb, 5400, nullptr, 0, 5504);
    gru_elem_kernel<<<(16384 * 1800 + 255) / 256, 256>>>(gbb + 5400, 1800);
    hm_launch(1, 15, px1A, px1A, px1A, 3648, 3648, 3648, 3648, 3648, 3648,
              pBd2H, pBd2L, 3648, nullptr, 0, d2b, 1800, px3A, 1920, 1920);
    hm_launch(1, 15, px3A, px3A, px3A, 1920, 1920, 1920, 1920, 1920, 1920,
              pBd4H, pBd4L, 1920, nullptr, 0, d4b, 1800, px5A, 1920, 1920);
    hm_launch(2, 2, px1A, px3A, px5A, 3648, 1920, 1920, 3648, 5568, 7488,
              pBoH, pBoL, 7488, out, 140, ob, 140, nullptr, 0, 140);
}

// round 14
// speedup vs baseline: 3.3481x; 1.5305x over previous
#include <cuda_runtime.h>
#include <cuda_fp16.h>
#include <math.h>
#include <stdint.h>

typedef __half f16;

// ============================ scratch ============================
__device__ float g_Weff[400 * 400];
__device__ float g_beff[400];
__device__ float g_attn[16383 * 400];
__device__ float g_G[(size_t)16384 * 5504];
__device__ f16   g_flatA[(size_t)16384 * 1600];
__device__ f16   g_x1A[(size_t)16384 * 3648];
__device__ f16   g_x3A[(size_t)16384 * 1920];
__device__ f16   g_x5A[(size_t)16384 * 1920];
__device__ f16   g_BgfH[(size_t)5504 * 1600];
__device__ f16   g_BgfL[(size_t)5504 * 1600];
__device__ f16   g_BgbH[(size_t)5504 * 1600];
__device__ f16   g_BgbL[(size_t)5504 * 1600];
__device__ f16   g_Bd2H[(size_t)1920 * 3648];
__device__ f16   g_Bd2L[(size_t)1920 * 3648];
__device__ f16   g_Bd4H[(size_t)1920 * 1920];
__device__ f16   g_Bd4L[(size_t)1920 * 1920];
__device__ f16   g_BoH[(size_t)256 * 7488];
__device__ f16   g_BoL[(size_t)256 * 7488];

// ============================ ptx helpers (plain sm_103-legal) ============================
__device__ __forceinline__ uint32_t s2u(const void* p) {
    uint32_t a;
    asm("{ .reg .u64 t; cvta.to.shared.u64 t, %1; cvt.u32.u64 %0, t; }" : "=r"(a) : "l"(p));
    return a;
}
__device__ __forceinline__ void ldm_x4(uint32_t* r, uint32_t addr) {
    asm volatile("ldmatrix.sync.aligned.m8n8.x4.shared.b16 {%0,%1,%2,%3}, [%4];"
                 : "=r"(r[0]), "=r"(r[1]), "=r"(r[2]), "=r"(r[3]) : "r"(addr));
}
__device__ __forceinline__ void mma16816(float* c, const uint32_t* a, const uint32_t* b) {
    asm volatile("mma.sync.aligned.m16n8k16.row.col.f32.f16.f16.f32 "
                 "{%0,%1,%2,%3}, {%4,%5,%6,%7}, {%8,%9}, {%0,%1,%2,%3};"
                 : "+f"(c[0]), "+f"(c[1]), "+f"(c[2]), "+f"(c[3])
                 : "r"(a[0]), "r"(a[1]), "r"(a[2]), "r"(a[3]), "r"(b[0]), "r"(b[1]));
}
__device__ __forceinline__ void cp16(uint32_t saddr, const void* g) {
    asm volatile("cp.async.cg.shared.global [%0], [%1], 16;" :: "r"(saddr), "l"(g) : "memory");
}

// ============================ HMMA GEMM (fp16, weight-split 2-term, 3-stage) ============================
// C[16384, 128*gridX] = concat(A1|A2|A3)[16384, Ktot] @ Bt[Npad, Ktot]^T
// A: single fp16. B: fp16 hi/lo digit pair. acc += A*Bhi + A*Blo (fp32 accum).
// EPI 0: C = acc + bias(col<biasN). EPI 1: elu(acc+bias) -> fp16 OA.
// EPI 2: C[col<Nvalid] = acc + bias.
#define PITCH 40                   // f16 elems per smem row (80B; conflict-free)
#define TILE_B (128 * PITCH * 2)   // 10240
#define STAGE_B (3 * TILE_B)       // 30720 (A, Bhi, Blo)
#define NSTAGE 3

template<int EPI>
__global__ __launch_bounds__(256, 2)
void hmma_gemm(const f16* __restrict__ A1, const f16* __restrict__ A2, const f16* __restrict__ A3,
               int lda1, int lda2, int lda3, int kb1, int kb2, int Ktot,
               const f16* __restrict__ BH, const f16* __restrict__ BL, int ldb,
               float* __restrict__ C, int ldc,
               const float* __restrict__ bias, int biasN,
               f16* __restrict__ OA, int ldo, int Nvalid)
{
    extern __shared__ char smem[];
    const uint32_t su = s2u(smem);
    const int tid = threadIdx.x;
    const int lane = tid & 31;
    const int wid = tid >> 5;
    const int warp_m = wid & 1;       // 2 x 64 rows
    const int warp_n = wid >> 1;      // 4 x 32 cols
    const size_t rowA = (size_t)blockIdx.y * 128;
    const size_t rowB = (size_t)blockIdx.x * 128;
    const int NCH = Ktot / 32;

    const int ldRow0 = tid >> 2, ldC0 = (tid & 3);
    const int ldRow1 = (tid + 256) >> 2, ldC1 = ldC0;

    auto issue = [&](int ch, int s) {
        const int k0 = ch * 32;
        const f16* pA; int kl; size_t lda;
        if (k0 < kb1)      { pA = A1; kl = k0;       lda = (size_t)lda1; }
        else if (k0 < kb2) { pA = A2; kl = k0 - kb1; lda = (size_t)lda2; }
        else               { pA = A3; kl = k0 - kb2; lda = (size_t)lda3; }
        uint32_t st = su + s * STAGE_B;
        uint32_t d0 = st + ldRow0 * (PITCH * 2) + ldC0 * 16;
        uint32_t d1 = st + ldRow1 * (PITCH * 2) + ldC1 * 16;
        size_t a0 = (rowA + ldRow0) * lda + kl + ldC0 * 8;
        size_t a1 = (rowA + ldRow1) * lda + kl + ldC1 * 8;
        size_t b0 = (rowB + ldRow0) * (size_t)ldb + k0 + ldC0 * 8;
        size_t b1 = (rowB + ldRow1) * (size_t)ldb + k0 + ldC1 * 8;
        cp16(d0,              pA + a0);  cp16(d1,              pA + a1);
        cp16(d0 + TILE_B,     BH + b0);  cp16(d1 + TILE_B,     BH + b1);
        cp16(d0 + 2 * TILE_B, BL + b0);  cp16(d1 + 2 * TILE_B, BL + b1);
        asm volatile("cp.async.commit_group;" ::: "memory");
    };

    float acc[4][4][4];
#pragma unroll
    for (int i = 0; i < 4; i++)
#pragma unroll
        for (int j = 0; j < 4; j++)
#pragma unroll
            for (int k = 0; k < 4; k++) acc[i][j][k] = 0.f;

    issue(0, 0);
    if (NCH > 1) issue(1, 1);

    const int aLRow = lane & 15, aKH = lane >> 4;
    const int bRow = (lane & 7) + ((lane >> 4) << 3);
    const int bKH = (lane >> 3) & 1;

    for (int ch = 0; ch < NCH; ch++) {
        const int s = ch % NSTAGE;
        if (ch + 1 < NCH) {
            asm volatile("cp.async.wait_group 1;" ::: "memory");   // chunk ch complete
        } else {
            asm volatile("cp.async.wait_group 0;" ::: "memory");
        }
        __syncthreads();
        if (ch + 2 < NCH) issue(ch + 2, (ch + 2) % NSTAGE);

        const uint32_t st = su + s * STAGE_B;
#pragma unroll
        for (int kk2 = 0; kk2 < 2; kk2++) {
            const int kcol = kk2 * 16;
            uint32_t bH[4][2], bL[4][2];
#pragma unroll
            for (int np = 0; np < 2; np++) {
                uint32_t ad = st + TILE_B + (warp_n * 32 + np * 16 + bRow) * (PITCH * 2) + (kcol + 8 * bKH) * 2;
                uint32_t t[4];
                ldm_x4(t, ad);
                bH[np * 2][0] = t[0]; bH[np * 2][1] = t[1];
                bH[np * 2 + 1][0] = t[2]; bH[np * 2 + 1][1] = t[3];
                ldm_x4(t, ad + TILE_B);
                bL[np * 2][0] = t[0]; bL[np * 2][1] = t[1];
                bL[np * 2 + 1][0] = t[2]; bL[np * 2 + 1][1] = t[3];
            }
            uint32_t a[4][4];
#pragma unroll
            for (int mf = 0; mf < 4; mf++) {
                uint32_t ad = st + (warp_m * 64 + mf * 16 + aLRow) * (PITCH * 2) + (kcol + 8 * aKH) * 2;
                ldm_x4(a[mf], ad);
            }
#pragma unroll
            for (int mf = 0; mf < 4; mf++)
#pragma unroll
                for (int nf = 0; nf < 4; nf++)
                    mma16816(acc[mf][nf], a[mf], bH[nf]);     // A*Bhi x16
#pragma unroll
            for (int mf = 0; mf < 4; mf++)
#pragma unroll
                for (int nf = 0; nf < 4; nf++)
                    mma16816(acc[mf][nf], a[mf], bL[nf]);     // A*Blo x16
        }
    }

    // ---------------- epilogue ----------------
    const int rBase = (int)rowA + warp_m * 64 + (lane >> 2);
    const int cBase = (int)rowB + warp_n * 32 + (lane & 3) * 2;
#pragma unroll
    for (int mf = 0; mf < 4; mf++) {
#pragma unroll
        for (int half = 0; half < 2; half++) {
            const size_t r = rBase + mf * 16 + half * 8;
#pragma unroll
            for (int nf = 0; nf < 4; nf++) {
                const int col = cBase + nf * 8;
                float v0 = acc[mf][nf][half * 2 + 0];
                float v1 = acc[mf][nf][half * 2 + 1];
                if (EPI == 0) {
                    if (col + 0 < biasN) v0 += bias[col + 0];
                    if (col + 1 < biasN) v1 += bias[col + 1];
                    *reinterpret_cast<float2*>(C + r * (size_t)ldc + col) = make_float2(v0, v1);
                } else if (EPI == 1) {
                    if (col + 0 < biasN) v0 += bias[col + 0];
                    if (col + 1 < biasN) v1 += bias[col + 1];
                    v0 = v0 > 0.f ? v0 : expm1f(v0);
                    v1 = v1 > 0.f ? v1 : expm1f(v1);
                    __half2 p = __floats2half2_rn(v0, v1);
                    *reinterpret_cast<__half2*>(OA + r * (size_t)ldo + col) = p;
                } else {
                    if (col + 0 < Nvalid) C[r * (size_t)ldc + col + 0] = v0 + bias[col + 0];
                    if (col + 1 < Nvalid) C[r * (size_t)ldc + col + 1] = v1 + bias[col + 1];
                }
            }
        }
    }
}

// ============================ weight transpose + fp16 hi/lo split ============================
__global__ void convB_kernel(const float* __restrict__ B, int Ksrc, int Nsrc, int ldbsrc,
                             f16* __restrict__ BtH, f16* __restrict__ BtL, int ldbt, int kOff)
{
    __shared__ float t[32][33];
    int k0 = blockIdx.x * 32, n0 = blockIdx.y * 32;
    int tx = threadIdx.x, ty = threadIdx.y;
#pragma unroll
    for (int i = 0; i < 4; i++) {
        int k = k0 + ty + i * 8, n = n0 + tx;
        t[ty + i * 8][tx] = (k < Ksrc && n < Nsrc) ? B[(size_t)k * ldbsrc + n] : 0.f;
    }
    __syncthreads();
#pragma unroll
    for (int i = 0; i < 4; i++) {
        int n = n0 + ty + i * 8, k = k0 + tx;
        float v = t[tx][ty + i * 8];
        f16 h = __float2half(v);
        size_t o = (size_t)n * ldbt + kOff + k;
        BtH[o] = h;
        BtL[o] = __float2half(v - __half2float(h));
    }
}

// ============================ SIMT SGEMM (front-end only) ============================
#define BM 128
#define BN 128
#define BK 8
__global__ __launch_bounds__(256, 2)
void sgemm_kernel(const float* __restrict__ A, const float* __restrict__ B,
                  float* __restrict__ C, const float* __restrict__ bias,
                  int M, int N, int K, int lda, int ldb, int ldc, int flags, int kChunk)
{
    __shared__ float As[BK][BM];
    __shared__ float Bs[BK][BN];
    const int tid = threadIdx.x;
    const int tx = tid & 15, ty = tid >> 4;
    const int rowBase = blockIdx.y * BM, colBase = blockIdx.x * BN;
    const int kStart = blockIdx.z * kChunk;
    const int kEnd = min(kStart + kChunk, K);
    float acc[8][8];
#pragma unroll
    for (int i = 0; i < 8; i++)
#pragma unroll
        for (int j = 0; j < 8; j++) acc[i][j] = 0.f;
    const int aRow = tid >> 1, aCol = (tid & 1) * 4, gARow = rowBase + aRow;
    const int bRow = tid >> 5, bCol = (tid & 31) * 4, gBCol = colBase + bCol;
    for (int k0 = kStart; k0 < kEnd; k0 += BK) {
        float4 av = make_float4(0.f, 0.f, 0.f, 0.f);
        if (gARow < M) av = *reinterpret_cast<const float4*>(A + (size_t)gARow * lda + k0 + aCol);
        As[aCol + 0][aRow] = av.x; As[aCol + 1][aRow] = av.y;
        As[aCol + 2][aRow] = av.z; As[aCol + 3][aRow] = av.w;
        float4 bv = make_float4(0.f, 0.f, 0.f, 0.f);
        if (gBCol < N) bv = *reinterpret_cast<const float4*>(B + (size_t)(k0 + bRow) * ldb + gBCol);
        *reinterpret_cast<float4*>(&Bs[bRow][bCol]) = bv;
        __syncthreads();
#pragma unroll
        for (int kk = 0; kk < BK; kk++) {
            float4 a0 = *reinterpret_cast<const float4*>(&As[kk][ty * 8]);
            float4 a1 = *reinterpret_cast<const float4*>(&As[kk][ty * 8 + 4]);
            float4 b0 = *reinterpret_cast<const float4*>(&Bs[kk][tx * 8]);
            float4 b1 = *reinterpret_cast<const float4*>(&Bs[kk][tx * 8 + 4]);
            float a[8] = {a0.x, a0.y, a0.z, a0.w, a1.x, a1.y, a1.z, a1.w};
            float b[8] = {b0.x, b0.y, b0.z, b0.w, b1.x, b1.y, b1.z, b1.w};
#pragma unroll
            for (int i = 0; i < 8; i++)
#pragma unroll
                for (int j = 0; j < 8; j++) acc[i][j] = fmaf(a[i], b[j], acc[i][j]);
        }
        __syncthreads();
    }
#pragma unroll
    for (int i = 0; i < 8; i++) {
        int row = rowBase + ty * 8 + i;
        if (row >= M) continue;
#pragma unroll
        for (int j = 0; j < 8; j++) {
            int col = colBase + tx * 8 + j;
            if (col >= N) continue;
            float v = acc[i][j];
            size_t off = (size_t)row * ldc + col;
            if (flags & 4) atomicAdd(&C[off], v);
            else { if (bias) v += bias[col]; C[off] = v; }
        }
    }
}

// ============================ small helpers ============================
__global__ void zero_weff_kernel()
{
    int i = blockIdx.x * 256 + threadIdx.x;
    if (i < 400 * 400) g_Weff[i] = 0.f;
}
__global__ void beff_kernel(const float* __restrict__ bv, const float* __restrict__ Wo,
                            const float* __restrict__ bo)
{
    int d = blockIdx.x * 256 + threadIdx.x;
    if (d >= 400) return;
    float acc = bo[d];
    for (int j = 0; j < 6400; j++) acc = fmaf(bv[j], Wo[(size_t)j * 400 + d], acc);
    g_beff[d] = acc;
}
__global__ void build_flat_f16(const float* __restrict__ x)
{
    int idx = blockIdx.x * 256 + threadIdx.x;
    const int total = 16384 * 1200;
    float v; size_t dst;
    if (idx < total) {
        int b = idx / 1200, c = idx - b * 1200;
        v = x[idx]; dst = (size_t)b * 1600 + c;
    } else if (idx < total + 400) {
        int d = idx - total;
        v = x[800 + d]; dst = 1200 + d;
    } else return;
    g_flatA[dst] = __float2half(v);
}
__global__ void pad_x1_kernel()
{
    int i = blockIdx.x * 256 + threadIdx.x;
    if (i >= 16384 * 48) return;
    int b = i / 48, c = 3600 + i % 48;
    g_x1A[(size_t)b * 3648 + c] = __float2half(0.f);
}

__device__ __forceinline__ float blockReduceSum(float v, float* sh)
{
#pragma unroll
    for (int o = 16; o > 0; o >>= 1) v += __shfl_xor_sync(0xffffffffu, v, o);
    int lane = threadIdx.x & 31, warp = threadIdx.x >> 5;
    if (lane == 0) sh[warp] = v;
    __syncthreads();
    if (warp == 0) {
        float r = (lane < 8) ? sh[lane] : 0.f;
#pragma unroll
        for (int o = 4; o > 0; o >>= 1) r += __shfl_xor_sync(0xffffffffu, r, o);
        if (lane == 0) sh[0] = r;
    }
    __syncthreads();
    float r = sh[0];
    __syncthreads();
    return r;
}

__global__ __launch_bounds__(256)
void frontend_kernel(const float* __restrict__ x,
                     const float* __restrict__ ln1g, const float* __restrict__ ln1b,
                     const float* __restrict__ w1,  const float* __restrict__ fb1,
                     const float* __restrict__ w2,  const float* __restrict__ fb2,
                     const float* __restrict__ ln2g, const float* __restrict__ ln2b)
{
    int b = blockIdx.x;
    const float* xe = x + (size_t)(b + 1) * 1200 + 800;
    const float* at = g_attn + (size_t)b * 400;
    __shared__ float red[32];
    int t = threadIdx.x;
    float sv[2], o1[2], s2v[2];
    int dIdx[2], cnt = 0;
    float sum = 0.f, sq = 0.f;
    for (int d = t; d < 400; d += 256) {
        float v = xe[d] + at[d];
        sv[cnt] = v; dIdx[cnt] = d; cnt++;
        sum += v; sq += v * v;
    }
    sum = blockReduceSum(sum, red);
    sq  = blockReduceSum(sq, red);
    float mean = sum * (1.f / 400.f);
    float var  = sq * (1.f / 400.f) - mean * mean;
    float rstd = rsqrtf(var + 1e-6f);
    float t0 = 0.f, t1 = 0.f;
    for (int i = 0; i < cnt; i++) {
        int d = dIdx[i];
        float o = (sv[i] - mean) * rstd * ln1g[d] + ln1b[d];
        o1[i] = o;
        t0 = fmaf(o, w1[2 * d], t0);
        t1 = fmaf(o, w1[2 * d + 1], t1);
    }
    t0 = blockReduceSum(t0, red);
    t1 = blockReduceSum(t1, red);
    t0 = fmaxf(t0 + fb1[0], 0.f);
    t1 = fmaxf(t1 + fb1[1], 0.f);
    sum = 0.f; sq = 0.f;
    for (int i = 0; i < cnt; i++) {
        int d = dIdx[i];
        float v = o1[i] + t0 * w2[d] + t1 * w2[400 + d] + fb2[d];
        s2v[i] = v; sum += v; sq += v * v;
    }
    sum = blockReduceSum(sum, red);
    sq  = blockReduceSum(sq, red);
    mean = sum * (1.f / 400.f);
    var  = sq * (1.f / 400.f) - mean * mean;
    rstd = rsqrtf(var + 1e-6f);
    size_t base = (size_t)(b + 1) * 1600 + 1200;
    for (int i = 0; i < cnt; i++) {
        int d = dIdx[i];
        g_flatA[base + d] = __float2half((s2v[i] - mean) * rstd * ln2g[d] + ln2b[d]);
    }
}

__global__ void gru_elem_kernel(const float* __restrict__ Brow1, int colOff)
{
    int idx = blockIdx.x * 256 + threadIdx.x;
    if (idx >= 16384 * 1800) return;
    int b = idx / 1800, j = idx - b * 1800;
    const float* g = g_G + (size_t)b * 5504;
    float z = 1.f / (1.f + expf(-(g[j] + Brow1[j])));
    float r = 1.f / (1.f + expf(-(g[1800 + j] + Brow1[1800 + j])));
    float hv = g[3600 + j] + r * Brow1[3600 + j];
    float hh = (hv > 0.f) ? hv : expm1f(hv);
    g_x1A[(size_t)b * 3648 + colOff + j] = __float2half((1.f - z) * hh);
}

// ============================ host ============================
#define HM_SMEM (NSTAGE * STAGE_B)   // 92160

static void hm_launch(int epi, int nTiles,
                      const f16* A1, const f16* A2, const f16* A3,
                      int lda1, int lda2, int lda3, int kb1, int kb2, int Ktot,
                      const f16* BH, const f16* BL, int ldb,
                      float* C, int ldc, const float* bias, int biasN,
                      f16* OA, int ldo, int Nvalid)
{
    dim3 grid(nTiles, 128);
    if (epi == 0)
        hmma_gemm<0><<<grid, 256, HM_SMEM>>>(A1, A2, A3, lda1, lda2, lda3, kb1, kb2, Ktot,
                                             BH, BL, ldb, C, ldc, bias, biasN, OA, ldo, Nvalid);
    else if (epi == 1)
        hmma_gemm<1><<<grid, 256, HM_SMEM>>>(A1, A2, A3, lda1, lda2, lda3, kb1, kb2, Ktot,
                                             BH, BL, ldb, C, ldc, bias, biasN, OA, ldo, Nvalid);
    else
        hmma_gemm<2><<<grid, 256, HM_SMEM>>>(A1, A2, A3, lda1, lda2, lda3, kb1, kb2, Ktot,
                                             BH, BL, ldb, C, ldc, bias, biasN, OA, ldo, Nvalid);
}

extern "C" void kernel_launch(void* const* d_in, const int* in_sizes, int n_in,
                              void* d_out, int out_size)
{
    (void)n_in; (void)out_size;
    const float* x  = (const float*)d_in[0];
    const float* Wv = (const float*)d_in[5];
    const float* bv = (const float*)d_in[6];
    const float* Wo = (const float*)d_in[7];
    const float* bo = (const float*)d_in[8];

    bool sigOrder = (in_sizes[10] == 400);
    const float *ln1g, *ln1b, *w1, *fb1, *w2, *fb2, *ln2g, *ln2b;
    const float *gfk, *gfb, *gbk, *gbb, *d2w, *d2b, *d4w, *d4b, *ow, *ob;
    if (sigOrder) {
        ln1g = (const float*)d_in[9];  ln1b = (const float*)d_in[10];
        w1   = (const float*)d_in[11]; fb1  = (const float*)d_in[12];
        w2   = (const float*)d_in[13]; fb2  = (const float*)d_in[14];
        ln2g = (const float*)d_in[15]; ln2b = (const float*)d_in[16];
        gfk  = (const float*)d_in[17]; gfb  = (const float*)d_in[19];
        gbk  = (const float*)d_in[20]; gbb  = (const float*)d_in[22];
        d2w  = (const float*)d_in[23]; d2b  = (const float*)d_in[24];
        d4w  = (const float*)d_in[25]; d4b  = (const float*)d_in[26];
        ow   = (const float*)d_in[27]; ob   = (const float*)d_in[28];
    } else {
        ln1b = (const float*)d_in[9];
        w1   = (const float*)d_in[10]; fb1  = (const float*)d_in[11];
        w2   = (const float*)d_in[12]; fb2  = (const float*)d_in[13];
        ln2b = (const float*)d_in[14];
        gfk  = (const float*)d_in[15]; gfb  = (const float*)d_in[17];
        gbk  = (const float*)d_in[18]; gbb  = (const float*)d_in[20];
        d2w  = (const float*)d_in[21]; d2b  = (const float*)d_in[22];
        d4w  = (const float*)d_in[23]; d4b  = (const float*)d_in[24];
        ow   = (const float*)d_in[25]; ob   = (const float*)d_in[26];
        ln1g = (const float*)d_in[27]; ln2g = (const float*)d_in[28];
    }

    float *pWeff, *pbeff, *pattn, *pG;
    f16 *pflatA, *px1A, *px3A, *px5A;
    f16 *pBgfH, *pBgfL, *pBgbH, *pBgbL, *pBd2H, *pBd2L, *pBd4H, *pBd4L, *pBoH, *pBoL;
    cudaGetSymbolAddress((void**)&pWeff, g_Weff);
    cudaGetSymbolAddress((void**)&pbeff, g_beff);
    cudaGetSymbolAddress((void**)&pattn, g_attn);
    cudaGetSymbolAddress((void**)&pG, g_G);
    cudaGetSymbolAddress((void**)&pflatA, g_flatA);
    cudaGetSymbolAddress((void**)&px1A, g_x1A);
    cudaGetSymbolAddress((void**)&px3A, g_x3A);
    cudaGetSymbolAddress((void**)&px5A, g_x5A);
    cudaGetSymbolAddress((void**)&pBgfH, g_BgfH);
    cudaGetSymbolAddress((void**)&pBgfL, g_BgfL);
    cudaGetSymbolAddress((void**)&pBgbH, g_BgbH);
    cudaGetSymbolAddress((void**)&pBgbL, g_BgbL);
    cudaGetSymbolAddress((void**)&pBd2H, g_Bd2H);
    cudaGetSymbolAddress((void**)&pBd2L, g_Bd2L);
    cudaGetSymbolAddress((void**)&pBd4H, g_Bd4H);
    cudaGetSymbolAddress((void**)&pBd4L, g_Bd4L);
    cudaGetSymbolAddress((void**)&pBoH, g_BoH);
    cudaGetSymbolAddress((void**)&pBoL, g_BoL);
    float* out = (float*)d_out;

    cudaFuncSetAttribute(hmma_gemm<0>, cudaFuncAttributeMaxDynamicSharedMemorySize, HM_SMEM);
    cudaFuncSetAttribute(hmma_gemm<1>, cudaFuncAttributeMaxDynamicSharedMemorySize, HM_SMEM);
    cudaFuncSetAttribute(hmma_gemm<2>, cudaFuncAttributeMaxDynamicSharedMemorySize, HM_SMEM);

    // --- front-end (SIMT fp32) ---
    zero_weff_kernel<<<(400 * 400 + 255) / 256, 256>>>();
    { dim3 g(4, 4, 8); sgemm_kernel<<<g, 256>>>(Wv, Wo, pWeff, nullptr, 400, 400, 6400, 6400, 400, 400, 4, 800); }
    beff_kernel<<<2, 256>>>(bv, Wo, bo);
    { dim3 g(4, 128, 1); sgemm_kernel<<<g, 256>>>(x + 2000, pWeff, pattn, pbeff, 16383, 400, 400, 1200, 400, 400, 0, 400); }
    build_flat_f16<<<(16384 * 1200 + 400 + 255) / 256, 256>>>(x);
    frontend_kernel<<<16383, 256>>>(x, ln1g, ln1b, w1, fb1, w2, fb2, ln2g, ln2b);

    // --- weight conversion (transpose + fp16 hi/lo split, padded) ---
    { dim3 g(1600 / 32, 5504 / 32); convB_kernel<<<g, dim3(32, 8)>>>(gfk, 1600, 5400, 5400, pBgfH, pBgfL, 1600, 0); }
    { dim3 g(1600 / 32, 5504 / 32); convB_kernel<<<g, dim3(32, 8)>>>(gbk, 1600, 5400, 5400, pBgbH, pBgbL, 1600, 0); }
    { dim3 g(3648 / 32, 1920 / 32); convB_kernel<<<g, dim3(32, 8)>>>(d2w, 3600, 1800, 1800, pBd2H, pBd2L, 3648, 0); }
    { dim3 g(1920 / 32, 1920 / 32); convB_kernel<<<g, dim3(32, 8)>>>(d4w, 1800, 1800, 1800, pBd4H, pBd4L, 1920, 0); }
    { dim3 g(3648 / 32, 256 / 32);  convB_kernel<<<g, dim3(32, 8)>>>(ow,              3600, 140, 140, pBoH, pBoL, 7488, 0); }
    { dim3 g(1920 / 32, 256 / 32);  convB_kernel<<<g, dim3(32, 8)>>>(ow + 3600 * 140, 1800, 140, 140, pBoH, pBoL, 7488, 3648); }
    { dim3 g(1920 / 32, 256 / 32);  convB_kernel<<<g, dim3(32, 8)>>>(ow + 5400 * 140, 1800, 140, 140, pBoH, pBoL, 7488, 5568); }
    pad_x1_kernel<<<(16384 * 48 + 255) / 256, 256>>>();

    // --- tensor-core GEMMs (mma.sync fp16, weight-split 2-term, 3-stage pipe) ---
    hm_launch(0, 43, pflatA, pflatA, pflatA, 1600, 1600, 1600, 1600, 1600, 1600,
              pBgfH, pBgfL, 1600, pG, 5504, gfb, 5400, nullptr, 0, 5504);
    gru_elem_kernel<<<(16384 * 1800 + 255) / 256, 256>>>(gfb + 5400, 0);
    hm_launch(0, 43, pflatA, pflatA, pflatA, 1600, 1600, 1600, 1600, 1600, 1600,
              pBgbH, pBgbL, 1600, pG, 5504, gbb, 5400, nullptr, 0, 5504);
    gru_elem_kernel<<<(16384 * 1800 + 255) / 256, 256>>>(gbb + 5400, 1800);
    hm_launch(1, 15, px1A, px1A, px1A, 3648, 3648, 3648, 3648, 3648, 3648,
              pBd2H, pBd2L, 3648, nullptr, 0, d2b, 1800, px3A, 1920, 1920);
    hm_launch(1, 15, px3A, px3A, px3A, 1920, 1920, 1920, 1920, 1920, 1920,
              pBd4H, pBd4L, 1920, nullptr, 0, d4b, 1800, px5A, 1920, 1920);
    hm_launch(2, 2, px1A, px3A, px5A, 3648, 1920, 1920, 3648, 5568, 7488,
              pBoH, pBoL, 7488, out, 140, ob, 140, nullptr, 0, 140);
}

// round 15
// speedup vs baseline: 4.1988x; 1.2541x over previous
#include <cuda_runtime.h>
#include <cuda_fp16.h>
#include <math.h>
#include <stdint.h>

typedef __half f16;

// ============================ scratch ============================
__device__ float g_Weff[400 * 400];
__device__ float g_beff[400];
__device__ float g_attn[(size_t)16384 * 400];
__device__ f16   g_G[(size_t)16384 * 5504];          // GRU preacts (f16)
__device__ f16   g_xeP[(size_t)16384 * 416];         // padded xe (f16)
__device__ f16   g_WeffH[(size_t)512 * 416];
__device__ f16   g_WeffL[(size_t)512 * 416];
__device__ f16   g_flatA[(size_t)16384 * 1600];
__device__ f16   g_x1A[(size_t)16384 * 3648];
__device__ f16   g_x3A[(size_t)16384 * 1920];
__device__ f16   g_x5A[(size_t)16384 * 1920];
__device__ f16   g_Bgf[(size_t)5504 * 1600];         // GRU weights: single f16
__device__ f16   g_Bgb[(size_t)5504 * 1600];
__device__ f16   g_Bd2H[(size_t)1920 * 3648];
__device__ f16   g_Bd2L[(size_t)1920 * 3648];
__device__ f16   g_Bd4H[(size_t)1920 * 1920];
__device__ f16   g_Bd4L[(size_t)1920 * 1920];
__device__ f16   g_BoH[(size_t)256 * 7488];
__device__ f16   g_BoL[(size_t)256 * 7488];

// ============================ ptx helpers (plain sm_103-legal) ============================
__device__ __forceinline__ uint32_t s2u(const void* p) {
    uint32_t a;
    asm("{ .reg .u64 t; cvta.to.shared.u64 t, %1; cvt.u32.u64 %0, t; }" : "=r"(a) : "l"(p));
    return a;
}
__device__ __forceinline__ void ldm_x4(uint32_t* r, uint32_t addr) {
    asm volatile("ldmatrix.sync.aligned.m8n8.x4.shared.b16 {%0,%1,%2,%3}, [%4];"
                 : "=r"(r[0]), "=r"(r[1]), "=r"(r[2]), "=r"(r[3]) : "r"(addr));
}
__device__ __forceinline__ void mma16816(float* c, const uint32_t* a, const uint32_t* b) {
    asm volatile("mma.sync.aligned.m16n8k16.row.col.f32.f16.f16.f32 "
                 "{%0,%1,%2,%3}, {%4,%5,%6,%7}, {%8,%9}, {%0,%1,%2,%3};"
                 : "+f"(c[0]), "+f"(c[1]), "+f"(c[2]), "+f"(c[3])
                 : "r"(a[0]), "r"(a[1]), "r"(a[2]), "r"(a[3]), "r"(b[0]), "r"(b[1]));
}
__device__ __forceinline__ void cp16(uint32_t saddr, const void* g) {
    asm volatile("cp.async.cg.shared.global [%0], [%1], 16;" :: "r"(saddr), "l"(g) : "memory");
}

// ============================ HMMA GEMM (fp16, TERMS = 1|2, 3-stage) ============================
// C/OA[16384, 128*gridX] = concat(A1|A2|A3)[16384, Ktot] @ Bt[Npad, Ktot]^T
// TERMS=2: B = hi/lo pair, acc += A*Bhi + A*Blo.  TERMS=1: acc += A*B.
// EPI 1: elu(acc+bias[col<biasN]) -> f16 OA.
// EPI 2: C[col<Nvalid] = acc + bias (fp32).
// EPI 3: (acc+bias[col<biasN]) -> f16 OA.
#define PITCH 40                   // f16 elems per smem row (80B; conflict-free)
#define TILE_B (128 * PITCH * 2)   // 10240
#define NSTAGE 3

template<int EPI, int TERMS>
__global__ __launch_bounds__(256, 2)
void hmma_gemm(const f16* __restrict__ A1, const f16* __restrict__ A2, const f16* __restrict__ A3,
               int lda1, int lda2, int lda3, int kb1, int kb2, int Ktot,
               const f16* __restrict__ BH, const f16* __restrict__ BL, int ldb,
               float* __restrict__ C, int ldc,
               const float* __restrict__ bias, int biasN,
               f16* __restrict__ OA, int ldo, int Nvalid)
{
    constexpr int STAGE_B = (1 + TERMS) * TILE_B;
    extern __shared__ char smem[];
    const uint32_t su = s2u(smem);
    const int tid = threadIdx.x;
    const int lane = tid & 31;
    const int wid = tid >> 5;
    const int warp_m = wid & 1;       // 2 x 64 rows
    const int warp_n = wid >> 1;      // 4 x 32 cols
    const size_t rowA = (size_t)blockIdx.y * 128;
    const size_t rowB = (size_t)blockIdx.x * 128;
    const int NCH = Ktot / 32;

    const int ldRow0 = tid >> 2, ldC0 = (tid & 3);
    const int ldRow1 = (tid + 256) >> 2, ldC1 = ldC0;

    auto issue = [&](int ch, int s) {
        const int k0 = ch * 32;
        const f16* pA; int kl; size_t lda;
        if (k0 < kb1)      { pA = A1; kl = k0;       lda = (size_t)lda1; }
        else if (k0 < kb2) { pA = A2; kl = k0 - kb1; lda = (size_t)lda2; }
        else               { pA = A3; kl = k0 - kb2; lda = (size_t)lda3; }
        uint32_t st = su + s * STAGE_B;
        uint32_t d0 = st + ldRow0 * (PITCH * 2) + ldC0 * 16;
        uint32_t d1 = st + ldRow1 * (PITCH * 2) + ldC1 * 16;
        size_t a0 = (rowA + ldRow0) * lda + kl + ldC0 * 8;
        size_t a1 = (rowA + ldRow1) * lda + kl + ldC1 * 8;
        size_t b0 = (rowB + ldRow0) * (size_t)ldb + k0 + ldC0 * 8;
        size_t b1 = (rowB + ldRow1) * (size_t)ldb + k0 + ldC1 * 8;
        cp16(d0,          pA + a0);  cp16(d1,          pA + a1);
        cp16(d0 + TILE_B, BH + b0);  cp16(d1 + TILE_B, BH + b1);
        if (TERMS == 2) {
            cp16(d0 + 2 * TILE_B, BL + b0);  cp16(d1 + 2 * TILE_B, BL + b1);
        }
        asm volatile("cp.async.commit_group;" ::: "memory");
    };

    float acc[4][4][4];
#pragma unroll
    for (int i = 0; i < 4; i++)
#pragma unroll
        for (int j = 0; j < 4; j++)
#pragma unroll
            for (int k = 0; k < 4; k++) acc[i][j][k] = 0.f;

    issue(0, 0);
    if (NCH > 1) issue(1, 1);

    const int aLRow = lane & 15, aKH = lane >> 4;
    const int bRow = (lane & 7) + ((lane >> 4) << 3);
    const int bKH = (lane >> 3) & 1;

    for (int ch = 0; ch < NCH; ch++) {
        const int s = ch % NSTAGE;
        if (ch + 1 < NCH) {
            asm volatile("cp.async.wait_group 1;" ::: "memory");
        } else {
            asm volatile("cp.async.wait_group 0;" ::: "memory");
        }
        __syncthreads();
        if (ch + 2 < NCH) issue(ch + 2, (ch + 2) % NSTAGE);

        const uint32_t st = su + s * STAGE_B;
#pragma unroll
        for (int kk2 = 0; kk2 < 2; kk2++) {
            const int kcol = kk2 * 16;
            uint32_t bH[4][2], bL[4][2];
#pragma unroll
            for (int np = 0; np < 2; np++) {
                uint32_t ad = st + TILE_B + (warp_n * 32 + np * 16 + bRow) * (PITCH * 2) + (kcol + 8 * bKH) * 2;
                uint32_t t[4];
                ldm_x4(t, ad);
                bH[np * 2][0] = t[0]; bH[np * 2][1] = t[1];
                bH[np * 2 + 1][0] = t[2]; bH[np * 2 + 1][1] = t[3];
                if (TERMS == 2) {
                    ldm_x4(t, ad + TILE_B);
                    bL[np * 2][0] = t[0]; bL[np * 2][1] = t[1];
                    bL[np * 2 + 1][0] = t[2]; bL[np * 2 + 1][1] = t[3];
                }
            }
            uint32_t a[4][4];
#pragma unroll
            for (int mf = 0; mf < 4; mf++) {
                uint32_t ad = st + (warp_m * 64 + mf * 16 + aLRow) * (PITCH * 2) + (kcol + 8 * aKH) * 2;
                ldm_x4(a[mf], ad);
            }
#pragma unroll
            for (int mf = 0; mf < 4; mf++)
#pragma unroll
                for (int nf = 0; nf < 4; nf++)
                    mma16816(acc[mf][nf], a[mf], bH[nf]);
            if (TERMS == 2) {
#pragma unroll
                for (int mf = 0; mf < 4; mf++)
#pragma unroll
                    for (int nf = 0; nf < 4; nf++)
                        mma16816(acc[mf][nf], a[mf], bL[nf]);
            }
        }
    }

    // ---------------- epilogue ----------------
    const int rBase = (int)rowA + warp_m * 64 + (lane >> 2);
    const int cBase = (int)rowB + warp_n * 32 + (lane & 3) * 2;
#pragma unroll
    for (int mf = 0; mf < 4; mf++) {
#pragma unroll
        for (int half = 0; half < 2; half++) {
            const size_t r = rBase + mf * 16 + half * 8;
#pragma unroll
            for (int nf = 0; nf < 4; nf++) {
                const int col = cBase + nf * 8;
                float v0 = acc[mf][nf][half * 2 + 0];
                float v1 = acc[mf][nf][half * 2 + 1];
                if (EPI == 1 || EPI == 3) {
                    if (col + 0 < biasN) v0 += bias[col + 0];
                    if (col + 1 < biasN) v1 += bias[col + 1];
                    if (EPI == 1) {
                        v0 = v0 > 0.f ? v0 : expm1f(v0);
                        v1 = v1 > 0.f ? v1 : expm1f(v1);
                    }
                    __half2 p = __floats2half2_rn(v0, v1);
                    *reinterpret_cast<__half2*>(OA + r * (size_t)ldo + col) = p;
                } else {
                    if (col + 0 < Nvalid) C[r * (size_t)ldc + col + 0] = v0 + bias[col + 0];
                    if (col + 1 < Nvalid) C[r * (size_t)ldc + col + 1] = v1 + bias[col + 1];
                }
            }
        }
    }
}

// ============================ weight transpose + split ============================
// 2-output (hi/lo) variant
__global__ void convB_kernel(const float* __restrict__ B, int Ksrc, int Nsrc, int ldbsrc,
                             f16* __restrict__ BtH, f16* __restrict__ BtL, int ldbt, int kOff)
{
    __shared__ float t[32][33];
    int k0 = blockIdx.x * 32, n0 = blockIdx.y * 32;
    int tx = threadIdx.x, ty = threadIdx.y;
#pragma unroll
    for (int i = 0; i < 4; i++) {
        int k = k0 + ty + i * 8, n = n0 + tx;
        t[ty + i * 8][tx] = (k < Ksrc && n < Nsrc) ? B[(size_t)k * ldbsrc + n] : 0.f;
    }
    __syncthreads();
#pragma unroll
    for (int i = 0; i < 4; i++) {
        int n = n0 + ty + i * 8, k = k0 + tx;
        float v = t[tx][ty + i * 8];
        f16 h = __float2half(v);
        size_t o = (size_t)n * ldbt + kOff + k;
        BtH[o] = h;
        BtL[o] = __float2half(v - __half2float(h));
    }
}
// single-output variant (GRU weights)
__global__ void convB1_kernel(const float* __restrict__ B, int Ksrc, int Nsrc, int ldbsrc,
                              f16* __restrict__ Bt, int ldbt)
{
    __shared__ float t[32][33];
    int k0 = blockIdx.x * 32, n0 = blockIdx.y * 32;
    int tx = threadIdx.x, ty = threadIdx.y;
#pragma unroll
    for (int i = 0; i < 4; i++) {
        int k = k0 + ty + i * 8, n = n0 + tx;
        t[ty + i * 8][tx] = (k < Ksrc && n < Nsrc) ? B[(size_t)k * ldbsrc + n] : 0.f;
    }
    __syncthreads();
#pragma unroll
    for (int i = 0; i < 4; i++) {
        int n = n0 + ty + i * 8, k = k0 + tx;
        Bt[(size_t)n * ldbt + k] = __float2half(t[tx][ty + i * 8]);
    }
}

// ============================ SIMT SGEMM (Weff only) ============================
#define BM 128
#define BN 128
#define BK 8
__global__ __launch_bounds__(256, 2)
void sgemm_kernel(const float* __restrict__ A, const float* __restrict__ B,
                  float* __restrict__ C, const float* __restrict__ bias,
                  int M, int N, int K, int lda, int ldb, int ldc, int flags, int kChunk)
{
    __shared__ float As[BK][BM];
    __shared__ float Bs[BK][BN];
    const int tid = threadIdx.x;
    const int tx = tid & 15, ty = tid >> 4;
    const int rowBase = blockIdx.y * BM, colBase = blockIdx.x * BN;
    const int kStart = blockIdx.z * kChunk;
    const int kEnd = min(kStart + kChunk, K);
    float acc[8][8];
#pragma unroll
    for (int i = 0; i < 8; i++)
#pragma unroll
        for (int j = 0; j < 8; j++) acc[i][j] = 0.f;
    const int aRow = tid >> 1, aCol = (tid & 1) * 4, gARow = rowBase + aRow;
    const int bRow = tid >> 5, bCol = (tid & 31) * 4, gBCol = colBase + bCol;
    for (int k0 = kStart; k0 < kEnd; k0 += BK) {
        float4 av = make_float4(0.f, 0.f, 0.f, 0.f);
        if (gARow < M) av = *reinterpret_cast<const float4*>(A + (size_t)gARow * lda + k0 + aCol);
        As[aCol + 0][aRow] = av.x; As[aCol + 1][aRow] = av.y;
        As[aCol + 2][aRow] = av.z; As[aCol + 3][aRow] = av.w;
        float4 bv = make_float4(0.f, 0.f, 0.f, 0.f);
        if (gBCol < N) bv = *reinterpret_cast<const float4*>(B + (size_t)(k0 + bRow) * ldb + gBCol);
        *reinterpret_cast<float4*>(&Bs[bRow][bCol]) = bv;
        __syncthreads();
#pragma unroll
        for (int kk = 0; kk < BK; kk++) {
            float4 a0 = *reinterpret_cast<const float4*>(&As[kk][ty * 8]);
            float4 a1 = *reinterpret_cast<const float4*>(&As[kk][ty * 8 + 4]);
            float4 b0 = *reinterpret_cast<const float4*>(&Bs[kk][tx * 8]);
            float4 b1 = *reinterpret_cast<const float4*>(&Bs[kk][tx * 8 + 4]);
            float a[8] = {a0.x, a0.y, a0.z, a0.w, a1.x, a1.y, a1.z, a1.w};
            float b[8] = {b0.x, b0.y, b0.z, b0.w, b1.x, b1.y, b1.z, b1.w};
#pragma unroll
            for (int i = 0; i < 8; i++)
#pragma unroll
                for (int j = 0; j < 8; j++) acc[i][j] = fmaf(a[i], b[j], acc[i][j]);
        }
        __syncthreads();
    }
#pragma unroll
    for (int i = 0; i < 8; i++) {
        int row = rowBase + ty * 8 + i;
        if (row >= M) continue;
#pragma unroll
        for (int j = 0; j < 8; j++) {
            int col = colBase + tx * 8 + j;
            if (col >= N) continue;
            float v = acc[i][j];
            size_t off = (size_t)row * ldc + col;
            if (flags & 4) atomicAdd(&C[off], v);
            else { if (bias) v += bias[col]; C[off] = v; }
        }
    }
}

// ============================ small helpers ============================
__global__ void zero_weff_kernel()
{
    int i = blockIdx.x * 256 + threadIdx.x;
    if (i < 400 * 400) g_Weff[i] = 0.f;
}
__global__ void beff_kernel(const float* __restrict__ bv, const float* __restrict__ Wo,
                            const float* __restrict__ bo)
{
    int d = blockIdx.x * 256 + threadIdx.x;
    if (d >= 400) return;
    float acc = bo[d];
    for (int j = 0; j < 6400; j++) acc = fmaf(bv[j], Wo[(size_t)j * 400 + d], acc);
    g_beff[d] = acc;
}
// xeP[r, k] = x[(r+1)*1200 + 800 + k] (f16), zero-padded in k >= 400 and row 16383.
__global__ void build_xeP(const float* __restrict__ x)
{
    int idx = blockIdx.x * 256 + threadIdx.x;
    if (idx >= 16384 * 416) return;
    int r = idx / 416, k = idx - r * 416;
    float v = (k < 400 && r < 16383) ? x[(size_t)(r + 1) * 1200 + 800 + k] : 0.f;
    g_xeP[idx] = __float2half(v);
}
__global__ void build_flat_f16(const float* __restrict__ x)
{
    int idx = blockIdx.x * 256 + threadIdx.x;
    const int total = 16384 * 1200;
    float v; size_t dst;
    if (idx < total) {
        int b = idx / 1200, c = idx - b * 1200;
        v = x[idx]; dst = (size_t)b * 1600 + c;
    } else if (idx < total + 400) {
        int d = idx - total;
        v = x[800 + d]; dst = 1200 + d;
    } else return;
    g_flatA[dst] = __float2half(v);
}
__global__ void pad_x1_kernel()
{
    int i = blockIdx.x * 256 + threadIdx.x;
    if (i >= 16384 * 48) return;
    int b = i / 48, c = 3600 + i % 48;
    g_x1A[(size_t)b * 3648 + c] = __float2half(0.f);
}

__device__ __forceinline__ float blockReduceSum(float v, float* sh)
{
#pragma unroll
    for (int o = 16; o > 0; o >>= 1) v += __shfl_xor_sync(0xffffffffu, v, o);
    int lane = threadIdx.x & 31, warp = threadIdx.x >> 5;
    if (lane == 0) sh[warp] = v;
    __syncthreads();
    if (warp == 0) {
        float r = (lane < 8) ? sh[lane] : 0.f;
#pragma unroll
        for (int o = 4; o > 0; o >>= 1) r += __shfl_xor_sync(0xffffffffu, r, o);
        if (lane == 0) sh[0] = r;
    }
    __syncthreads();
    float r = sh[0];
    __syncthreads();
    return r;
}

__global__ __launch_bounds__(256)
void frontend_kernel(const float* __restrict__ x,
                     const float* __restrict__ ln1g, const float* __restrict__ ln1b,
                     const float* __restrict__ w1,  const float* __restrict__ fb1,
                     const float* __restrict__ w2,  const float* __restrict__ fb2,
                     const float* __restrict__ ln2g, const float* __restrict__ ln2b)
{
    int b = blockIdx.x;
    const float* xe = x + (size_t)(b + 1) * 1200 + 800;
    const float* at = g_attn + (size_t)b * 400;
    __shared__ float red[32];
    int t = threadIdx.x;
    float sv[2], o1[2], s2v[2];
    int dIdx[2], cnt = 0;
    float sum = 0.f, sq = 0.f;
    for (int d = t; d < 400; d += 256) {
        float v = xe[d] + at[d];
        sv[cnt] = v; dIdx[cnt] = d; cnt++;
        sum += v; sq += v * v;
    }
    sum = blockReduceSum(sum, red);
    sq  = blockReduceSum(sq, red);
    float mean = sum * (1.f / 400.f);
    float var  = sq * (1.f / 400.f) - mean * mean;
    float rstd = rsqrtf(var + 1e-6f);
    float t0 = 0.f, t1 = 0.f;
    for (int i = 0; i < cnt; i++) {
        int d = dIdx[i];
        float o = (sv[i] - mean) * rstd * ln1g[d] + ln1b[d];
        o1[i] = o;
        t0 = fmaf(o, w1[2 * d], t0);
        t1 = fmaf(o, w1[2 * d + 1], t1);
    }
    t0 = blockReduceSum(t0, red);
    t1 = blockReduceSum(t1, red);
    t0 = fmaxf(t0 + fb1[0], 0.f);
    t1 = fmaxf(t1 + fb1[1], 0.f);
    sum = 0.f; sq = 0.f;
    for (int i = 0; i < cnt; i++) {
        int d = dIdx[i];
        float v = o1[i] + t0 * w2[d] + t1 * w2[400 + d] + fb2[d];
        s2v[i] = v; sum += v; sq += v * v;
    }
    sum = blockReduceSum(sum, red);
    sq  = blockReduceSum(sq, red);
    mean = sum * (1.f / 400.f);
    var  = sq * (1.f / 400.f) - mean * mean;
    rstd = rsqrtf(var + 1e-6f);
    size_t base = (size_t)(b + 1) * 1600 + 1200;
    for (int i = 0; i < cnt; i++) {
        int d = dIdx[i];
        g_flatA[base + d] = __float2half((s2v[i] - mean) * rstd * ln2g[d] + ln2b[d]);
    }
}

// GRU elementwise (h0 == 0), preacts in f16.
__global__ void gru_elem_kernel(const float* __restrict__ Brow1, int colOff)
{
    int idx = blockIdx.x * 256 + threadIdx.x;
    if (idx >= 16384 * 1800) return;
    int b = idx / 1800, j = idx - b * 1800;
    const f16* g = g_G + (size_t)b * 5504;
    float z = 1.f / (1.f + expf(-(__half2float(g[j]) + Brow1[j])));
    float r = 1.f / (1.f + expf(-(__half2float(g[1800 + j]) + Brow1[1800 + j])));
    float hv = __half2float(g[3600 + j]) + r * Brow1[3600 + j];
    float hh = (hv > 0.f) ? hv : expm1f(hv);
    g_x1A[(size_t)b * 3648 + colOff + j] = __float2half((1.f - z) * hh);
}

// ============================ host ============================
#define SM_T2 (NSTAGE * 3 * TILE_B)   // 92160
#define SM_T1 (NSTAGE * 2 * TILE_B)   // 61440

extern "C" void kernel_launch(void* const* d_in, const int* in_sizes, int n_in,
                              void* d_out, int out_size)
{
    (void)n_in; (void)out_size;
    const float* x  = (const float*)d_in[0];
    const float* Wv = (const float*)d_in[5];
    const float* bv = (const float*)d_in[6];
    const float* Wo = (const float*)d_in[7];
    const float* bo = (const float*)d_in[8];

    bool sigOrder = (in_sizes[10] == 400);
    const float *ln1g, *ln1b, *w1, *fb1, *w2, *fb2, *ln2g, *ln2b;
    const float *gfk, *gfb, *gbk, *gbb, *d2w, *d2b, *d4w, *d4b, *ow, *ob;
    if (sigOrder) {
        ln1g = (const float*)d_in[9];  ln1b = (const float*)d_in[10];
        w1   = (const float*)d_in[11]; fb1  = (const float*)d_in[12];
        w2   = (const float*)d_in[13]; fb2  = (const float*)d_in[14];
        ln2g = (const float*)d_in[15]; ln2b = (const float*)d_in[16];
        gfk  = (const float*)d_in[17]; gfb  = (const float*)d_in[19];
        gbk  = (const float*)d_in[20]; gbb  = (const float*)d_in[22];
        d2w  = (const float*)d_in[23]; d2b  = (const float*)d_in[24];
        d4w  = (const float*)d_in[25]; d4b  = (const float*)d_in[26];
        ow   = (const float*)d_in[27]; ob   = (const float*)d_in[28];
    } else {
        ln1b = (const float*)d_in[9];
        w1   = (const float*)d_in[10]; fb1  = (const float*)d_in[11];
        w2   = (const float*)d_in[12]; fb2  = (const float*)d_in[13];
        ln2b = (const float*)d_in[14];
        gfk  = (const float*)d_in[15]; gfb  = (const float*)d_in[17];
        gbk  = (const float*)d_in[18]; gbb  = (const float*)d_in[20];
        d2w  = (const float*)d_in[21]; d2b  = (const float*)d_in[22];
        d4w  = (const float*)d_in[23]; d4b  = (const float*)d_in[24];
        ow   = (const float*)d_in[25]; ob   = (const float*)d_in[26];
        ln1g = (const float*)d_in[27]; ln2g = (const float*)d_in[28];
    }

    float *pWeff, *pbeff, *pattn;
    f16 *pG, *pxeP, *pWeH, *pWeL, *pflatA, *px1A, *px3A, *px5A;
    f16 *pBgf, *pBgb, *pBd2H, *pBd2L, *pBd4H, *pBd4L, *pBoH, *pBoL;
    cudaGetSymbolAddress((void**)&pWeff, g_Weff);
    cudaGetSymbolAddress((void**)&pbeff, g_beff);
    cudaGetSymbolAddress((void**)&pattn, g_attn);
    cudaGetSymbolAddress((void**)&pG, g_G);
    cudaGetSymbolAddress((void**)&pxeP, g_xeP);
    cudaGetSymbolAddress((void**)&pWeH, g_WeffH);
    cudaGetSymbolAddress((void**)&pWeL, g_WeffL);
    cudaGetSymbolAddress((void**)&pflatA, g_flatA);
    cudaGetSymbolAddress((void**)&px1A, g_x1A);
    cudaGetSymbolAddress((void**)&px3A, g_x3A);
    cudaGetSymbolAddress((void**)&px5A, g_x5A);
    cudaGetSymbolAddress((void**)&pBgf, g_Bgf);
    cudaGetSymbolAddress((void**)&pBgb, g_Bgb);
    cudaGetSymbolAddress((void**)&pBd2H, g_Bd2H);
    cudaGetSymbolAddress((void**)&pBd2L, g_Bd2L);
    cudaGetSymbolAddress((void**)&pBd4H, g_Bd4H);
    cudaGetSymbolAddress((void**)&pBd4L, g_Bd4L);
    cudaGetSymbolAddress((void**)&pBoH, g_BoH);
    cudaGetSymbolAddress((void**)&pBoL, g_BoL);
    float* out = (float*)d_out;

    cudaFuncSetAttribute(hmma_gemm<1, 2>, cudaFuncAttributeMaxDynamicSharedMemorySize, SM_T2);
    cudaFuncSetAttribute(hmma_gemm<2, 2>, cudaFuncAttributeMaxDynamicSharedMemorySize, SM_T2);
    cudaFuncSetAttribute(hmma_gemm<3, 1>, cudaFuncAttributeMaxDynamicSharedMemorySize, SM_T1);

    // --- front-end ---
    zero_weff_kernel<<<(400 * 400 + 255) / 256, 256>>>();
    { dim3 g(4, 4, 8); sgemm_kernel<<<g, 256>>>(Wv, Wo, pWeff, nullptr, 400, 400, 6400, 6400, 400, 400, 4, 800); }
    beff_kernel<<<2, 256>>>(bv, Wo, bo);
    // Weff -> transposed f16 hi/lo [512 x 416]
    { dim3 g(13, 16); convB_kernel<<<g, dim3(32, 8)>>>(pWeff, 400, 400, 400, pWeH, pWeL, 416, 0); }
    build_xeP<<<(16384 * 416 + 255) / 256, 256>>>(x);
    // attn = xeP @ WeffT^T + beff (tensor, 2-term, EPI2)
    { dim3 g(4, 128);
      hmma_gemm<2, 2><<<g, 256, SM_T2>>>(pxeP, pxeP, pxeP, 416, 416, 416, 416, 416, 416,
                                         pWeH, pWeL, 416, pattn, 400, pbeff, 400, nullptr, 0, 400); }
    build_flat_f16<<<(16384 * 1200 + 400 + 255) / 256, 256>>>(x);
    frontend_kernel<<<16383, 256>>>(x, ln1g, ln1b, w1, fb1, w2, fb2, ln2g, ln2b);

    // --- weight conversion ---
    { dim3 g(50, 172);  convB1_kernel<<<g, dim3(32, 8)>>>(gfk, 1600, 5400, 5400, pBgf, 1600); }
    { dim3 g(50, 172);  convB1_kernel<<<g, dim3(32, 8)>>>(gbk, 1600, 5400, 5400, pBgb, 1600); }
    { dim3 g(114, 60);  convB_kernel<<<g, dim3(32, 8)>>>(d2w, 3600, 1800, 1800, pBd2H, pBd2L, 3648, 0); }
    { dim3 g(60, 60);   convB_kernel<<<g, dim3(32, 8)>>>(d4w, 1800, 1800, 1800, pBd4H, pBd4L, 1920, 0); }
    { dim3 g(114, 8);   convB_kernel<<<g, dim3(32, 8)>>>(ow,              3600, 140, 140, pBoH, pBoL, 7488, 0); }
    { dim3 g(60, 8);    convB_kernel<<<g, dim3(32, 8)>>>(ow + 3600 * 140, 1800, 140, 140, pBoH, pBoL, 7488, 3648); }
    { dim3 g(60, 8);    convB_kernel<<<g, dim3(32, 8)>>>(ow + 5400 * 140, 1800, 140, 140, pBoH, pBoL, 7488, 5568); }
    pad_x1_kernel<<<(16384 * 48 + 255) / 256, 256>>>();

    // --- tensor-core GEMMs ---
    // GRU forward/backward: 1-term fp16, preacts -> f16 G (EPI3)
    { dim3 g(43, 128);
      hmma_gemm<3, 1><<<g, 256, SM_T1>>>(pflatA, pflatA, pflatA, 1600, 1600, 1600, 1600, 1600, 1600,
                                         pBgf, nullptr, 1600, nullptr, 0, gfb, 5400, pG, 5504, 5504); }
    gru_elem_kernel<<<(16384 * 1800 + 255) / 256, 256>>>(gfb + 5400, 0);
    { dim3 g(43, 128);
      hmma_gemm<3, 1><<<g, 256, SM_T1>>>(pflatA, pflatA, pflatA, 1600, 1600, 1600, 1600, 1600, 1600,
                                         pBgb, nullptr, 1600, nullptr, 0, gbb, 5400, pG, 5504, 5504); }
    gru_elem_kernel<<<(16384 * 1800 + 255) / 256, 256>>>(gbb + 5400, 1800);
    // x3 = elu(x1 @ d2w + b), 2-term
    { dim3 g(15, 128);
      hmma_gemm<1, 2><<<g, 256, SM_T2>>>(px1A, px1A, px1A, 3648, 3648, 3648, 3648, 3648, 3648,
                                         pBd2H, pBd2L, 3648, nullptr, 0, d2b, 1800, px3A, 1920, 1920); }
    // x5 = elu(x3 @ d4w + b), 2-term
    { dim3 g(15, 128);
      hmma_gemm<1, 2><<<g, 256, SM_T2>>>(px3A, px3A, px3A, 1920, 1920, 1920, 1920, 1920, 1920,
                                         pBd4H, pBd4L, 1920, nullptr, 0, d4b, 1800, px5A, 1920, 1920); }
    // out = [x1|x3|x5] @ Bo^T + ob, 2-term
    { dim3 g(2, 128);
      hmma_gemm<2, 2><<<g, 256, SM_T2>>>(px1A, px3A, px5A, 3648, 1920, 1920, 3648, 5568, 7488,
                                         pBoH, pBoL, 7488, out, 140, ob, 140, nullptr, 0, 140); }
}

// round 16
// speedup vs baseline: 4.9272x; 1.1735x over previous
#include <cuda_runtime.h>
#include <cuda_fp16.h>
#include <math.h>
#include <stdint.h>

typedef __half f16;

// ============================ scratch ============================
__device__ float g_Weff[400 * 400];
__device__ float g_beff[400];
__device__ float g_attn[(size_t)16384 * 400];
__device__ f16   g_G[(size_t)16384 * 5504];          // GRU preacts (f16)
__device__ f16   g_xeP[(size_t)16384 * 416];         // padded xe (f16)
__device__ f16   g_WeffH[(size_t)512 * 416];
__device__ f16   g_WeffL[(size_t)512 * 416];
__device__ f16   g_flatA[(size_t)16384 * 1600];
__device__ f16   g_x1A[(size_t)16384 * 3648];
__device__ f16   g_x3A[(size_t)16384 * 1920];
__device__ f16   g_x5A[(size_t)16384 * 1920];
__device__ f16   g_Bgf[(size_t)5504 * 1600];         // 1-term weights (single f16)
__device__ f16   g_Bgb[(size_t)5504 * 1600];
__device__ f16   g_Bd2[(size_t)1920 * 3648];
__device__ f16   g_Bd4[(size_t)1920 * 1920];
__device__ f16   g_BoH[(size_t)256 * 7488];          // out stays 2-term
__device__ f16   g_BoL[(size_t)256 * 7488];

// ============================ ptx helpers (plain sm_103-legal) ============================
__device__ __forceinline__ uint32_t s2u(const void* p) {
    uint32_t a;
    asm("{ .reg .u64 t; cvta.to.shared.u64 t, %1; cvt.u32.u64 %0, t; }" : "=r"(a) : "l"(p));
    return a;
}
__device__ __forceinline__ void ldm_x4(uint32_t* r, uint32_t addr) {
    asm volatile("ldmatrix.sync.aligned.m8n8.x4.shared.b16 {%0,%1,%2,%3}, [%4];"
                 : "=r"(r[0]), "=r"(r[1]), "=r"(r[2]), "=r"(r[3]) : "r"(addr));
}
__device__ __forceinline__ void mma16816(float* c, const uint32_t* a, const uint32_t* b) {
    asm volatile("mma.sync.aligned.m16n8k16.row.col.f32.f16.f16.f32 "
                 "{%0,%1,%2,%3}, {%4,%5,%6,%7}, {%8,%9}, {%0,%1,%2,%3};"
                 : "+f"(c[0]), "+f"(c[1]), "+f"(c[2]), "+f"(c[3])
                 : "r"(a[0]), "r"(a[1]), "r"(a[2]), "r"(a[3]), "r"(b[0]), "r"(b[1]));
}
__device__ __forceinline__ void cp16(uint32_t saddr, const void* g) {
    asm volatile("cp.async.cg.shared.global [%0], [%1], 16;" :: "r"(saddr), "l"(g) : "memory");
}

// ============================ HMMA GEMM (fp16, TERMS = 1|2, 3-stage) ============================
// C/OA[16384, 128*gridX] = concat(A1|A2|A3)[16384, Ktot] @ Bt[Npad, Ktot]^T
// TERMS=2: B = hi/lo pair, acc += A*Bhi + A*Blo.  TERMS=1: acc += A*B.
// EPI 1: elu(acc+bias[col<biasN]) -> f16 OA.
// EPI 2: C[col<Nvalid] = acc + bias (fp32).
// EPI 3: (acc+bias[col<biasN]) -> f16 OA.
#define PITCH 40                   // f16 elems per smem row (80B; conflict-free)
#define TILE_B (128 * PITCH * 2)   // 10240
#define NSTAGE 3

template<int EPI, int TERMS>
__global__ __launch_bounds__(256, 2)
void hmma_gemm(const f16* __restrict__ A1, const f16* __restrict__ A2, const f16* __restrict__ A3,
               int lda1, int lda2, int lda3, int kb1, int kb2, int Ktot,
               const f16* __restrict__ BH, const f16* __restrict__ BL, int ldb,
               float* __restrict__ C, int ldc,
               const float* __restrict__ bias, int biasN,
               f16* __restrict__ OA, int ldo, int Nvalid)
{
    constexpr int STAGE_B = (1 + TERMS) * TILE_B;
    extern __shared__ char smem[];
    const uint32_t su = s2u(smem);
    const int tid = threadIdx.x;
    const int lane = tid & 31;
    const int wid = tid >> 5;
    const int warp_m = wid & 1;       // 2 x 64 rows
    const int warp_n = wid >> 1;      // 4 x 32 cols
    const size_t rowA = (size_t)blockIdx.y * 128;
    const size_t rowB = (size_t)blockIdx.x * 128;
    const int NCH = Ktot / 32;

    const int ldRow0 = tid >> 2, ldC0 = (tid & 3);
    const int ldRow1 = (tid + 256) >> 2, ldC1 = ldC0;

    auto issue = [&](int ch, int s) {
        const int k0 = ch * 32;
        const f16* pA; int kl; size_t lda;
        if (k0 < kb1)      { pA = A1; kl = k0;       lda = (size_t)lda1; }
        else if (k0 < kb2) { pA = A2; kl = k0 - kb1; lda = (size_t)lda2; }
        else               { pA = A3; kl = k0 - kb2; lda = (size_t)lda3; }
        uint32_t st = su + s * STAGE_B;
        uint32_t d0 = st + ldRow0 * (PITCH * 2) + ldC0 * 16;
        uint32_t d1 = st + ldRow1 * (PITCH * 2) + ldC1 * 16;
        size_t a0 = (rowA + ldRow0) * lda + kl + ldC0 * 8;
        size_t a1 = (rowA + ldRow1) * lda + kl + ldC1 * 8;
        size_t b0 = (rowB + ldRow0) * (size_t)ldb + k0 + ldC0 * 8;
        size_t b1 = (rowB + ldRow1) * (size_t)ldb + k0 + ldC1 * 8;
        cp16(d0,          pA + a0);  cp16(d1,          pA + a1);
        cp16(d0 + TILE_B, BH + b0);  cp16(d1 + TILE_B, BH + b1);
        if (TERMS == 2) {
            cp16(d0 + 2 * TILE_B, BL + b0);  cp16(d1 + 2 * TILE_B, BL + b1);
        }
        asm volatile("cp.async.commit_group;" ::: "memory");
    };

    float acc[4][4][4];
#pragma unroll
    for (int i = 0; i < 4; i++)
#pragma unroll
        for (int j = 0; j < 4; j++)
#pragma unroll
            for (int k = 0; k < 4; k++) acc[i][j][k] = 0.f;

    issue(0, 0);
    if (NCH > 1) issue(1, 1);

    const int aLRow = lane & 15, aKH = lane >> 4;
    const int bRow = (lane & 7) + ((lane >> 4) << 3);
    const int bKH = (lane >> 3) & 1;

    for (int ch = 0; ch < NCH; ch++) {
        const int s = ch % NSTAGE;
        if (ch + 1 < NCH) {
            asm volatile("cp.async.wait_group 1;" ::: "memory");
        } else {
            asm volatile("cp.async.wait_group 0;" ::: "memory");
        }
        __syncthreads();
        if (ch + 2 < NCH) issue(ch + 2, (ch + 2) % NSTAGE);

        const uint32_t st = su + s * STAGE_B;
#pragma unroll
        for (int kk2 = 0; kk2 < 2; kk2++) {
            const int kcol = kk2 * 16;
            uint32_t bH[4][2], bL[4][2];
#pragma unroll
            for (int np = 0; np < 2; np++) {
                uint32_t ad = st + TILE_B + (warp_n * 32 + np * 16 + bRow) * (PITCH * 2) + (kcol + 8 * bKH) * 2;
                uint32_t t[4];
                ldm_x4(t, ad);
                bH[np * 2][0] = t[0]; bH[np * 2][1] = t[1];
                bH[np * 2 + 1][0] = t[2]; bH[np * 2 + 1][1] = t[3];
                if (TERMS == 2) {
                    ldm_x4(t, ad + TILE_B);
                    bL[np * 2][0] = t[0]; bL[np * 2][1] = t[1];
                    bL[np * 2 + 1][0] = t[2]; bL[np * 2 + 1][1] = t[3];
                }
            }
            uint32_t a[4][4];
#pragma unroll
            for (int mf = 0; mf < 4; mf++) {
                uint32_t ad = st + (warp_m * 64 + mf * 16 + aLRow) * (PITCH * 2) + (kcol + 8 * aKH) * 2;
                ldm_x4(a[mf], ad);
            }
#pragma unroll
            for (int mf = 0; mf < 4; mf++)
#pragma unroll
                for (int nf = 0; nf < 4; nf++)
                    mma16816(acc[mf][nf], a[mf], bH[nf]);
            if (TERMS == 2) {
#pragma unroll
                for (int mf = 0; mf < 4; mf++)
#pragma unroll
                    for (int nf = 0; nf < 4; nf++)
                        mma16816(acc[mf][nf], a[mf], bL[nf]);
            }
        }
    }

    // ---------------- epilogue ----------------
    const int rBase = (int)rowA + warp_m * 64 + (lane >> 2);
    const int cBase = (int)rowB + warp_n * 32 + (lane & 3) * 2;
#pragma unroll
    for (int mf = 0; mf < 4; mf++) {
#pragma unroll
        for (int half = 0; half < 2; half++) {
            const size_t r = rBase + mf * 16 + half * 8;
#pragma unroll
            for (int nf = 0; nf < 4; nf++) {
                const int col = cBase + nf * 8;
                float v0 = acc[mf][nf][half * 2 + 0];
                float v1 = acc[mf][nf][half * 2 + 1];
                if (EPI == 1 || EPI == 3) {
                    if (col + 0 < biasN) v0 += bias[col + 0];
                    if (col + 1 < biasN) v1 += bias[col + 1];
                    if (EPI == 1) {
                        v0 = v0 > 0.f ? v0 : expm1f(v0);
                        v1 = v1 > 0.f ? v1 : expm1f(v1);
                    }
                    __half2 p = __floats2half2_rn(v0, v1);
                    *reinterpret_cast<__half2*>(OA + r * (size_t)ldo + col) = p;
                } else {
                    if (col + 0 < Nvalid) C[r * (size_t)ldc + col + 0] = v0 + bias[col + 0];
                    if (col + 1 < Nvalid) C[r * (size_t)ldc + col + 1] = v1 + bias[col + 1];
                }
            }
        }
    }
}

// ============================ weight transpose + split ============================
// 2-output (hi/lo) variant
__global__ void convB_kernel(const float* __restrict__ B, int Ksrc, int Nsrc, int ldbsrc,
                             f16* __restrict__ BtH, f16* __restrict__ BtL, int ldbt, int kOff)
{
    __shared__ float t[32][33];
    int k0 = blockIdx.x * 32, n0 = blockIdx.y * 32;
    int tx = threadIdx.x, ty = threadIdx.y;
#pragma unroll
    for (int i = 0; i < 4; i++) {
        int k = k0 + ty + i * 8, n = n0 + tx;
        t[ty + i * 8][tx] = (k < Ksrc && n < Nsrc) ? B[(size_t)k * ldbsrc + n] : 0.f;
    }
    __syncthreads();
#pragma unroll
    for (int i = 0; i < 4; i++) {
        int n = n0 + ty + i * 8, k = k0 + tx;
        float v = t[tx][ty + i * 8];
        f16 h = __float2half(v);
        size_t o = (size_t)n * ldbt + kOff + k;
        BtH[o] = h;
        BtL[o] = __float2half(v - __half2float(h));
    }
}
// single-output variant (1-term weights)
__global__ void convB1_kernel(const float* __restrict__ B, int Ksrc, int Nsrc, int ldbsrc,
                              f16* __restrict__ Bt, int ldbt)
{
    __shared__ float t[32][33];
    int k0 = blockIdx.x * 32, n0 = blockIdx.y * 32;
    int tx = threadIdx.x, ty = threadIdx.y;
#pragma unroll
    for (int i = 0; i < 4; i++) {
        int k = k0 + ty + i * 8, n = n0 + tx;
        t[ty + i * 8][tx] = (k < Ksrc && n < Nsrc) ? B[(size_t)k * ldbsrc + n] : 0.f;
    }
    __syncthreads();
#pragma unroll
    for (int i = 0; i < 4; i++) {
        int n = n0 + ty + i * 8, k = k0 + tx;
        Bt[(size_t)n * ldbt + k] = __float2half(t[tx][ty + i * 8]);
    }
}

// ============================ SIMT SGEMM (Weff only) ============================
#define BM 128
#define BN 128
#define BK 8
__global__ __launch_bounds__(256, 2)
void sgemm_kernel(const float* __restrict__ A, const float* __restrict__ B,
                  float* __restrict__ C, const float* __restrict__ bias,
                  int M, int N, int K, int lda, int ldb, int ldc, int flags, int kChunk)
{
    __shared__ float As[BK][BM];
    __shared__ float Bs[BK][BN];
    const int tid = threadIdx.x;
    const int tx = tid & 15, ty = tid >> 4;
    const int rowBase = blockIdx.y * BM, colBase = blockIdx.x * BN;
    const int kStart = blockIdx.z * kChunk;
    const int kEnd = min(kStart + kChunk, K);
    float acc[8][8];
#pragma unroll
    for (int i = 0; i < 8; i++)
#pragma unroll
        for (int j = 0; j < 8; j++) acc[i][j] = 0.f;
    const int aRow = tid >> 1, aCol = (tid & 1) * 4, gARow = rowBase + aRow;
    const int bRow = tid >> 5, bCol = (tid & 31) * 4, gBCol = colBase + bCol;
    for (int k0 = kStart; k0 < kEnd; k0 += BK) {
        float4 av = make_float4(0.f, 0.f, 0.f, 0.f);
        if (gARow < M) av = *reinterpret_cast<const float4*>(A + (size_t)gARow * lda + k0 + aCol);
        As[aCol + 0][aRow] = av.x; As[aCol + 1][aRow] = av.y;
        As[aCol + 2][aRow] = av.z; As[aCol + 3][aRow] = av.w;
        float4 bv = make_float4(0.f, 0.f, 0.f, 0.f);
        if (gBCol < N) bv = *reinterpret_cast<const float4*>(B + (size_t)(k0 + bRow) * ldb + gBCol);
        *reinterpret_cast<float4*>(&Bs[bRow][bCol]) = bv;
        __syncthreads();
#pragma unroll
        for (int kk = 0; kk < BK; kk++) {
            float4 a0 = *reinterpret_cast<const float4*>(&As[kk][ty * 8]);
            float4 a1 = *reinterpret_cast<const float4*>(&As[kk][ty * 8 + 4]);
            float4 b0 = *reinterpret_cast<const float4*>(&Bs[kk][tx * 8]);
            float4 b1 = *reinterpret_cast<const float4*>(&Bs[kk][tx * 8 + 4]);
            float a[8] = {a0.x, a0.y, a0.z, a0.w, a1.x, a1.y, a1.z, a1.w};
            float b[8] = {b0.x, b0.y, b0.z, b0.w, b1.x, b1.y, b1.z, b1.w};
#pragma unroll
            for (int i = 0; i < 8; i++)
#pragma unroll
                for (int j = 0; j < 8; j++) acc[i][j] = fmaf(a[i], b[j], acc[i][j]);
        }
        __syncthreads();
    }
#pragma unroll
    for (int i = 0; i < 8; i++) {
        int row = rowBase + ty * 8 + i;
        if (row >= M) continue;
#pragma unroll
        for (int j = 0; j < 8; j++) {
            int col = colBase + tx * 8 + j;
            if (col >= N) continue;
            float v = acc[i][j];
            size_t off = (size_t)row * ldc + col;
            if (flags & 4) atomicAdd(&C[off], v);
            else { if (bias) v += bias[col]; C[off] = v; }
        }
    }
}

// ============================ small helpers ============================
__global__ void zero_weff_kernel()
{
    int i = blockIdx.x * 256 + threadIdx.x;
    if (i < 400 * 400) g_Weff[i] = 0.f;
}
__global__ void beff_kernel(const float* __restrict__ bv, const float* __restrict__ Wo,
                            const float* __restrict__ bo)
{
    int d = blockIdx.x * 256 + threadIdx.x;
    if (d >= 400) return;
    float acc = bo[d];
    for (int j = 0; j < 6400; j++) acc = fmaf(bv[j], Wo[(size_t)j * 400 + d], acc);
    g_beff[d] = acc;
}
// xeP[r, k] = x[(r+1)*1200 + 800 + k] (f16), zero-padded in k >= 400 and row 16383.
__global__ void build_xeP(const float* __restrict__ x)
{
    int idx = blockIdx.x * 256 + threadIdx.x;
    if (idx >= 16384 * 416) return;
    int r = idx / 416, k = idx - r * 416;
    float v = (k < 400 && r < 16383) ? x[(size_t)(r + 1) * 1200 + 800 + k] : 0.f;
    g_xeP[idx] = __float2half(v);
}
__global__ void build_flat_f16(const float* __restrict__ x)
{
    int idx = blockIdx.x * 256 + threadIdx.x;
    const int total = 16384 * 1200;
    float v; size_t dst;
    if (idx < total) {
        int b = idx / 1200, c = idx - b * 1200;
        v = x[idx]; dst = (size_t)b * 1600 + c;
    } else if (idx < total + 400) {
        int d = idx - total;
        v = x[800 + d]; dst = 1200 + d;
    } else return;
    g_flatA[dst] = __float2half(v);
}
__global__ void pad_x1_kernel()
{
    int i = blockIdx.x * 256 + threadIdx.x;
    if (i >= 16384 * 48) return;
    int b = i / 48, c = 3600 + i % 48;
    g_x1A[(size_t)b * 3648 + c] = __float2half(0.f);
}

__device__ __forceinline__ float blockReduceSum(float v, float* sh)
{
#pragma unroll
    for (int o = 16; o > 0; o >>= 1) v += __shfl_xor_sync(0xffffffffu, v, o);
    int lane = threadIdx.x & 31, warp = threadIdx.x >> 5;
    if (lane == 0) sh[warp] = v;
    __syncthreads();
    if (warp == 0) {
        float r = (lane < 8) ? sh[lane] : 0.f;
#pragma unroll
        for (int o = 4; o > 0; o >>= 1) r += __shfl_xor_sync(0xffffffffu, r, o);
        if (lane == 0) sh[0] = r;
    }
    __syncthreads();
    float r = sh[0];
    __syncthreads();
    return r;
}

__global__ __launch_bounds__(256)
void frontend_kernel(const float* __restrict__ x,
                     const float* __restrict__ ln1g, const float* __restrict__ ln1b,
                     const float* __restrict__ w1,  const float* __restrict__ fb1,
                     const float* __restrict__ w2,  const float* __restrict__ fb2,
                     const float* __restrict__ ln2g, const float* __restrict__ ln2b)
{
    int b = blockIdx.x;
    const float* xe = x + (size_t)(b + 1) * 1200 + 800;
    const float* at = g_attn + (size_t)b * 400;
    __shared__ float red[32];
    int t = threadIdx.x;
    float sv[2], o1[2], s2v[2];
    int dIdx[2], cnt = 0;
    float sum = 0.f, sq = 0.f;
    for (int d = t; d < 400; d += 256) {
        float v = xe[d] + at[d];
        sv[cnt] = v; dIdx[cnt] = d; cnt++;
        sum += v; sq += v * v;
    }
    sum = blockReduceSum(sum, red);
    sq  = blockReduceSum(sq, red);
    float mean = sum * (1.f / 400.f);
    float var  = sq * (1.f / 400.f) - mean * mean;
    float rstd = rsqrtf(var + 1e-6f);
    float t0 = 0.f, t1 = 0.f;
    for (int i = 0; i < cnt; i++) {
        int d = dIdx[i];
        float o = (sv[i] - mean) * rstd * ln1g[d] + ln1b[d];
        o1[i] = o;
        t0 = fmaf(o, w1[2 * d], t0);
        t1 = fmaf(o, w1[2 * d + 1], t1);
    }
    t0 = blockReduceSum(t0, red);
    t1 = blockReduceSum(t1, red);
    t0 = fmaxf(t0 + fb1[0], 0.f);
    t1 = fmaxf(t1 + fb1[1], 0.f);
    sum = 0.f; sq = 0.f;
    for (int i = 0; i < cnt; i++) {
        int d = dIdx[i];
        float v = o1[i] + t0 * w2[d] + t1 * w2[400 + d] + fb2[d];
        s2v[i] = v; sum += v; sq += v * v;
    }
    sum = blockReduceSum(sum, red);
    sq  = blockReduceSum(sq, red);
    mean = sum * (1.f / 400.f);
    var  = sq * (1.f / 400.f) - mean * mean;
    rstd = rsqrtf(var + 1e-6f);
    size_t base = (size_t)(b + 1) * 1600 + 1200;
    for (int i = 0; i < cnt; i++) {
        int d = dIdx[i];
        g_flatA[base + d] = __float2half((s2v[i] - mean) * rstd * ln2g[d] + ln2b[d]);
    }
}

// GRU elementwise (h0 == 0), preacts in f16.
__global__ void gru_elem_kernel(const float* __restrict__ Brow1, int colOff)
{
    int idx = blockIdx.x * 256 + threadIdx.x;
    if (idx >= 16384 * 1800) return;
    int b = idx / 1800, j = idx - b * 1800;
    const f16* g = g_G + (size_t)b * 5504;
    float z = 1.f / (1.f + expf(-(__half2float(g[j]) + Brow1[j])));
    float r = 1.f / (1.f + expf(-(__half2float(g[1800 + j]) + Brow1[1800 + j])));
    float hv = __half2float(g[3600 + j]) + r * Brow1[3600 + j];
    float hh = (hv > 0.f) ? hv : expm1f(hv);
    g_x1A[(size_t)b * 3648 + colOff + j] = __float2half((1.f - z) * hh);
}

// ============================ host ============================
#define SM_T2 (NSTAGE * 3 * TILE_B)   // 92160
#define SM_T1 (NSTAGE * 2 * TILE_B)   // 61440

extern "C" void kernel_launch(void* const* d_in, const int* in_sizes, int n_in,
                              void* d_out, int out_size)
{
    (void)n_in; (void)out_size;
    const float* x  = (const float*)d_in[0];
    const float* Wv = (const float*)d_in[5];
    const float* bv = (const float*)d_in[6];
    const float* Wo = (const float*)d_in[7];
    const float* bo = (const float*)d_in[8];

    bool sigOrder = (in_sizes[10] == 400);
    const float *ln1g, *ln1b, *w1, *fb1, *w2, *fb2, *ln2g, *ln2b;
    const float *gfk, *gfb, *gbk, *gbb, *d2w, *d2b, *d4w, *d4b, *ow, *ob;
    if (sigOrder) {
        ln1g = (const float*)d_in[9];  ln1b = (const float*)d_in[10];
        w1   = (const float*)d_in[11]; fb1  = (const float*)d_in[12];
        w2   = (const float*)d_in[13]; fb2  = (const float*)d_in[14];
        ln2g = (const float*)d_in[15]; ln2b = (const float*)d_in[16];
        gfk  = (const float*)d_in[17]; gfb  = (const float*)d_in[19];
        gbk  = (const float*)d_in[20]; gbb  = (const float*)d_in[22];
        d2w  = (const float*)d_in[23]; d2b  = (const float*)d_in[24];
        d4w  = (const float*)d_in[25]; d4b  = (const float*)d_in[26];
        ow   = (const float*)d_in[27]; ob   = (const float*)d_in[28];
    } else {
        ln1b = (const float*)d_in[9];
        w1   = (const float*)d_in[10]; fb1  = (const float*)d_in[11];
        w2   = (const float*)d_in[12]; fb2  = (const float*)d_in[13];
        ln2b = (const float*)d_in[14];
        gfk  = (const float*)d_in[15]; gfb  = (const float*)d_in[17];
        gbk  = (const float*)d_in[18]; gbb  = (const float*)d_in[20];
        d2w  = (const float*)d_in[21]; d2b  = (const float*)d_in[22];
        d4w  = (const float*)d_in[23]; d4b  = (const float*)d_in[24];
        ow   = (const float*)d_in[25]; ob   = (const float*)d_in[26];
        ln1g = (const float*)d_in[27]; ln2g = (const float*)d_in[28];
    }

    float *pWeff, *pbeff, *pattn;
    f16 *pG, *pxeP, *pWeH, *pWeL, *pflatA, *px1A, *px3A, *px5A;
    f16 *pBgf, *pBgb, *pBd2, *pBd4, *pBoH, *pBoL;
    cudaGetSymbolAddress((void**)&pWeff, g_Weff);
    cudaGetSymbolAddress((void**)&pbeff, g_beff);
    cudaGetSymbolAddress((void**)&pattn, g_attn);
    cudaGetSymbolAddress((void**)&pG, g_G);
    cudaGetSymbolAddress((void**)&pxeP, g_xeP);
    cudaGetSymbolAddress((void**)&pWeH, g_WeffH);
    cudaGetSymbolAddress((void**)&pWeL, g_WeffL);
    cudaGetSymbolAddress((void**)&pflatA, g_flatA);
    cudaGetSymbolAddress((void**)&px1A, g_x1A);
    cudaGetSymbolAddress((void**)&px3A, g_x3A);
    cudaGetSymbolAddress((void**)&px5A, g_x5A);
    cudaGetSymbolAddress((void**)&pBgf, g_Bgf);
    cudaGetSymbolAddress((void**)&pBgb, g_Bgb);
    cudaGetSymbolAddress((void**)&pBd2, g_Bd2);
    cudaGetSymbolAddress((void**)&pBd4, g_Bd4);
    cudaGetSymbolAddress((void**)&pBoH, g_BoH);
    cudaGetSymbolAddress((void**)&pBoL, g_BoL);
    float* out = (float*)d_out;

    cudaFuncSetAttribute(hmma_gemm<1, 1>, cudaFuncAttributeMaxDynamicSharedMemorySize, SM_T1);
    cudaFuncSetAttribute(hmma_gemm<2, 2>, cudaFuncAttributeMaxDynamicSharedMemorySize, SM_T2);
    cudaFuncSetAttribute(hmma_gemm<3, 1>, cudaFuncAttributeMaxDynamicSharedMemorySize, SM_T1);

    // --- front-end ---
    zero_weff_kernel<<<(400 * 400 + 255) / 256, 256>>>();
    { dim3 g(4, 4, 8); sgemm_kernel<<<g, 256>>>(Wv, Wo, pWeff, nullptr, 400, 400, 6400, 6400, 400, 400, 4, 800); }
    beff_kernel<<<2, 256>>>(bv, Wo, bo);
    // Weff -> transposed f16 hi/lo [512 x 416]
    { dim3 g(13, 16); convB_kernel<<<g, dim3(32, 8)>>>(pWeff, 400, 400, 400, pWeH, pWeL, 416, 0); }
    build_xeP<<<(16384 * 416 + 255) / 256, 256>>>(x);
    // attn = xeP @ WeffT^T + beff (tensor, 2-term, EPI2)
    { dim3 g(4, 128);
      hmma_gemm<2, 2><<<g, 256, SM_T2>>>(pxeP, pxeP, pxeP, 416, 416, 416, 416, 416, 416,
                                         pWeH, pWeL, 416, pattn, 400, pbeff, 400, nullptr, 0, 400); }
    build_flat_f16<<<(16384 * 1200 + 400 + 255) / 256, 256>>>(x);
    frontend_kernel<<<16383, 256>>>(x, ln1g, ln1b, w1, fb1, w2, fb2, ln2g, ln2b);

    // --- weight conversion ---
    { dim3 g(50, 172);  convB1_kernel<<<g, dim3(32, 8)>>>(gfk, 1600, 5400, 5400, pBgf, 1600); }
    { dim3 g(50, 172);  convB1_kernel<<<g, dim3(32, 8)>>>(gbk, 1600, 5400, 5400, pBgb, 1600); }
    { dim3 g(114, 60);  convB1_kernel<<<g, dim3(32, 8)>>>(d2w, 3600, 1800, 1800, pBd2, 3648); }
    { dim3 g(60, 60);   convB1_kernel<<<g, dim3(32, 8)>>>(d4w, 1800, 1800, 1800, pBd4, 1920); }
    { dim3 g(114, 8);   convB_kernel<<<g, dim3(32, 8)>>>(ow,              3600, 140, 140, pBoH, pBoL, 7488, 0); }
    { dim3 g(60, 8);    convB_kernel<<<g, dim3(32, 8)>>>(ow + 3600 * 140, 1800, 140, 140, pBoH, pBoL, 7488, 3648); }
    { dim3 g(60, 8);    convB_kernel<<<g, dim3(32, 8)>>>(ow + 5400 * 140, 1800, 140, 140, pBoH, pBoL, 7488, 5568); }
    pad_x1_kernel<<<(16384 * 48 + 255) / 256, 256>>>();

    // --- tensor-core GEMMs ---
    // GRU forward/backward: 1-term fp16, preacts -> f16 G (EPI3)
    { dim3 g(43, 128);
      hmma_gemm<3, 1><<<g, 256, SM_T1>>>(pflatA, pflatA, pflatA, 1600, 1600, 1600, 1600, 1600, 1600,
                                         pBgf, nullptr, 1600, nullptr, 0, gfb, 5400, pG, 5504, 5504); }
    gru_elem_kernel<<<(16384 * 1800 + 255) / 256, 256>>>(gfb + 5400, 0);
    { dim3 g(43, 128);
      hmma_gemm<3, 1><<<g, 256, SM_T1>>>(pflatA, pflatA, pflatA, 1600, 1600, 1600, 1600, 1600, 1600,
                                         pBgb, nullptr, 1600, nullptr, 0, gbb, 5400, pG, 5504, 5504); }
    gru_elem_kernel<<<(16384 * 1800 + 255) / 256, 256>>>(gbb + 5400, 1800);
    // x3 = elu(x1 @ d2w + b), 1-term
    { dim3 g(15, 128);
      hmma_gemm<1, 1><<<g, 256, SM_T1>>>(px1A, px1A, px1A, 3648, 3648, 3648, 3648, 3648, 3648,
                                         pBd2, nullptr, 3648, nullptr, 0, d2b, 1800, px3A, 1920, 1920); }
    // x5 = elu(x3 @ d4w + b), 1-term
    { dim3 g(15, 128);
      hmma_gemm<1, 1><<<g, 256, SM_T1>>>(px3A, px3A, px3A, 1920, 1920, 1920, 1920, 1920, 1920,
                                         pBd4, nullptr, 1920, nullptr, 0, d4b, 1800, px5A, 1920, 1920); }
    // out = [x1|x3|x5] @ Bo^T + ob, 2-term
    { dim3 g(2, 128);
      hmma_gemm<2, 2><<<g, 256, SM_T2>>>(px1A, px3A, px5A, 3648, 1920, 1920, 3648, 5568, 7488,
                                         pBoH, pBoL, 7488, out, 140, ob, 140, nullptr, 0, 140); }
}

// round 17
// speedup vs baseline: 5.2383x; 1.0632x over previous
#include <cuda_runtime.h>
#include <cuda_fp16.h>
#include <math.h>
#include <stdint.h>

typedef __half f16;

// ============================ scratch ============================
__device__ float g_Weff[400 * 400];
__device__ float g_beff[400];
__device__ float g_attn[(size_t)16384 * 400];
__device__ f16   g_G[(size_t)16384 * 5504];          // GRU fwd preacts (f16)
__device__ f16   g_G2[(size_t)16384 * 5504];         // GRU bwd preacts (f16)
__device__ f16   g_xeP[(size_t)16384 * 416];         // padded xe (f16)
__device__ f16   g_WeffH[(size_t)512 * 416];
__device__ f16   g_WeffL[(size_t)512 * 416];
__device__ f16   g_flatA[(size_t)16384 * 1600];
__device__ f16   g_x1A[(size_t)16384 * 3648];
__device__ f16   g_x3A[(size_t)16384 * 1920];
__device__ f16   g_x5A[(size_t)16384 * 1920];
__device__ f16   g_Bgf[(size_t)5504 * 1600];         // 1-term weights (single f16)
__device__ f16   g_Bgb[(size_t)5504 * 1600];
__device__ f16   g_Bd2[(size_t)1920 * 3648];
__device__ f16   g_Bd4[(size_t)1920 * 1920];
__device__ f16   g_Bo[(size_t)256 * 7488];           // out now 1-term

// ============================ ptx helpers (plain sm_103-legal) ============================
__device__ __forceinline__ uint32_t s2u(const void* p) {
    uint32_t a;
    asm("{ .reg .u64 t; cvta.to.shared.u64 t, %1; cvt.u32.u64 %0, t; }" : "=r"(a) : "l"(p));
    return a;
}
__device__ __forceinline__ void ldm_x4(uint32_t* r, uint32_t addr) {
    asm volatile("ldmatrix.sync.aligned.m8n8.x4.shared.b16 {%0,%1,%2,%3}, [%4];"
                 : "=r"(r[0]), "=r"(r[1]), "=r"(r[2]), "=r"(r[3]) : "r"(addr));
}
__device__ __forceinline__ void mma16816(float* c, const uint32_t* a, const uint32_t* b) {
    asm volatile("mma.sync.aligned.m16n8k16.row.col.f32.f16.f16.f32 "
                 "{%0,%1,%2,%3}, {%4,%5,%6,%7}, {%8,%9}, {%0,%1,%2,%3};"
                 : "+f"(c[0]), "+f"(c[1]), "+f"(c[2]), "+f"(c[3])
                 : "r"(a[0]), "r"(a[1]), "r"(a[2]), "r"(a[3]), "r"(b[0]), "r"(b[1]));
}
__device__ __forceinline__ void cp16(uint32_t saddr, const void* g) {
    asm volatile("cp.async.cg.shared.global [%0], [%1], 16;" :: "r"(saddr), "l"(g) : "memory");
}

// ============================ HMMA GEMM (fp16, TERMS = 1|2, 3-stage) ============================
// C/OA[16384, 128*gridX] = concat(A1|A2|A3)[16384, Ktot] @ Bt[Npad, Ktot]^T
// TERMS=2: B = hi/lo pair, acc += A*Bhi + A*Blo.  TERMS=1: acc += A*B.
// EPI 1: elu(acc+bias[col<biasN]) -> f16 OA.
// EPI 2: C[col<Nvalid] = acc + bias (fp32).
// EPI 3: (acc+bias[col<biasN]) -> f16 OA.
#define PITCH 40                   // f16 elems per smem row (80B; conflict-free)
#define TILE_B (128 * PITCH * 2)   // 10240
#define NSTAGE 3

template<int EPI, int TERMS>
__global__ __launch_bounds__(256, 2)
void hmma_gemm(const f16* __restrict__ A1, const f16* __restrict__ A2, const f16* __restrict__ A3,
               int lda1, int lda2, int lda3, int kb1, int kb2, int Ktot,
               const f16* __restrict__ BH, const f16* __restrict__ BL, int ldb,
               float* __restrict__ C, int ldc,
               const float* __restrict__ bias, int biasN,
               f16* __restrict__ OA, int ldo, int Nvalid)
{
    constexpr int STAGE_B = (1 + TERMS) * TILE_B;
    extern __shared__ char smem[];
    const uint32_t su = s2u(smem);
    const int tid = threadIdx.x;
    const int lane = tid & 31;
    const int wid = tid >> 5;
    const int warp_m = wid & 1;       // 2 x 64 rows
    const int warp_n = wid >> 1;      // 4 x 32 cols
    const size_t rowA = (size_t)blockIdx.y * 128;
    const size_t rowB = (size_t)blockIdx.x * 128;
    const int NCH = Ktot / 32;

    const int ldRow0 = tid >> 2, ldC0 = (tid & 3);
    const int ldRow1 = (tid + 256) >> 2, ldC1 = ldC0;

    auto issue = [&](int ch, int s) {
        const int k0 = ch * 32;
        const f16* pA; int kl; size_t lda;
        if (k0 < kb1)      { pA = A1; kl = k0;       lda = (size_t)lda1; }
        else if (k0 < kb2) { pA = A2; kl = k0 - kb1; lda = (size_t)lda2; }
        else               { pA = A3; kl = k0 - kb2; lda = (size_t)lda3; }
        uint32_t st = su + s * STAGE_B;
        uint32_t d0 = st + ldRow0 * (PITCH * 2) + ldC0 * 16;
        uint32_t d1 = st + ldRow1 * (PITCH * 2) + ldC1 * 16;
        size_t a0 = (rowA + ldRow0) * lda + kl + ldC0 * 8;
        size_t a1 = (rowA + ldRow1) * lda + kl + ldC1 * 8;
        size_t b0 = (rowB + ldRow0) * (size_t)ldb + k0 + ldC0 * 8;
        size_t b1 = (rowB + ldRow1) * (size_t)ldb + k0 + ldC1 * 8;
        cp16(d0,          pA + a0);  cp16(d1,          pA + a1);
        cp16(d0 + TILE_B, BH + b0);  cp16(d1 + TILE_B, BH + b1);
        if (TERMS == 2) {
            cp16(d0 + 2 * TILE_B, BL + b0);  cp16(d1 + 2 * TILE_B, BL + b1);
        }
        asm volatile("cp.async.commit_group;" ::: "memory");
    };

    float acc[4][4][4];
#pragma unroll
    for (int i = 0; i < 4; i++)
#pragma unroll
        for (int j = 0; j < 4; j++)
#pragma unroll
            for (int k = 0; k < 4; k++) acc[i][j][k] = 0.f;

    issue(0, 0);
    if (NCH > 1) issue(1, 1);

    const int aLRow = lane & 15, aKH = lane >> 4;
    const int bRow = (lane & 7) + ((lane >> 4) << 3);
    const int bKH = (lane >> 3) & 1;

    for (int ch = 0; ch < NCH; ch++) {
        const int s = ch % NSTAGE;
        if (ch + 1 < NCH) {
            asm volatile("cp.async.wait_group 1;" ::: "memory");
        } else {
            asm volatile("cp.async.wait_group 0;" ::: "memory");
        }
        __syncthreads();
        if (ch + 2 < NCH) issue(ch + 2, (ch + 2) % NSTAGE);

        const uint32_t st = su + s * STAGE_B;
#pragma unroll
        for (int kk2 = 0; kk2 < 2; kk2++) {
            const int kcol = kk2 * 16;
            uint32_t bH[4][2], bL[4][2];
#pragma unroll
            for (int np = 0; np < 2; np++) {
                uint32_t ad = st + TILE_B + (warp_n * 32 + np * 16 + bRow) * (PITCH * 2) + (kcol + 8 * bKH) * 2;
                uint32_t t[4];
                ldm_x4(t, ad);
                bH[np * 2][0] = t[0]; bH[np * 2][1] = t[1];
                bH[np * 2 + 1][0] = t[2]; bH[np * 2 + 1][1] = t[3];
                if (TERMS == 2) {
                    ldm_x4(t, ad + TILE_B);
                    bL[np * 2][0] = t[0]; bL[np * 2][1] = t[1];
                    bL[np * 2 + 1][0] = t[2]; bL[np * 2 + 1][1] = t[3];
                }
            }
            uint32_t a[4][4];
#pragma unroll
            for (int mf = 0; mf < 4; mf++) {
                uint32_t ad = st + (warp_m * 64 + mf * 16 + aLRow) * (PITCH * 2) + (kcol + 8 * aKH) * 2;
                ldm_x4(a[mf], ad);
            }
#pragma unroll
            for (int mf = 0; mf < 4; mf++)
#pragma unroll
                for (int nf = 0; nf < 4; nf++)
                    mma16816(acc[mf][nf], a[mf], bH[nf]);
            if (TERMS == 2) {
#pragma unroll
                for (int mf = 0; mf < 4; mf++)
#pragma unroll
                    for (int nf = 0; nf < 4; nf++)
                        mma16816(acc[mf][nf], a[mf], bL[nf]);
            }
        }
    }

    // ---------------- epilogue ----------------
    const int rBase = (int)rowA + warp_m * 64 + (lane >> 2);
    const int cBase = (int)rowB + warp_n * 32 + (lane & 3) * 2;
#pragma unroll
    for (int mf = 0; mf < 4; mf++) {
#pragma unroll
        for (int half = 0; half < 2; half++) {
            const size_t r = rBase + mf * 16 + half * 8;
#pragma unroll
            for (int nf = 0; nf < 4; nf++) {
                const int col = cBase + nf * 8;
                float v0 = acc[mf][nf][half * 2 + 0];
                float v1 = acc[mf][nf][half * 2 + 1];
                if (EPI == 1 || EPI == 3) {
                    if (col + 0 < biasN) v0 += bias[col + 0];
                    if (col + 1 < biasN) v1 += bias[col + 1];
                    if (EPI == 1) {
                        v0 = v0 > 0.f ? v0 : (__expf(v0) - 1.f);
                        v1 = v1 > 0.f ? v1 : (__expf(v1) - 1.f);
                    }
                    __half2 p = __floats2half2_rn(v0, v1);
                    *reinterpret_cast<__half2*>(OA + r * (size_t)ldo + col) = p;
                } else {
                    if (col + 0 < Nvalid) C[r * (size_t)ldc + col + 0] = v0 + bias[col + 0];
                    if (col + 1 < Nvalid) C[r * (size_t)ldc + col + 1] = v1 + bias[col + 1];
                }
            }
        }
    }
}

// ============================ weight transpose + split ============================
__global__ void convB_kernel(const float* __restrict__ B, int Ksrc, int Nsrc, int ldbsrc,
                             f16* __restrict__ BtH, f16* __restrict__ BtL, int ldbt, int kOff)
{
    __shared__ float t[32][33];
    int k0 = blockIdx.x * 32, n0 = blockIdx.y * 32;
    int tx = threadIdx.x, ty = threadIdx.y;
#pragma unroll
    for (int i = 0; i < 4; i++) {
        int k = k0 + ty + i * 8, n = n0 + tx;
        t[ty + i * 8][tx] = (k < Ksrc && n < Nsrc) ? B[(size_t)k * ldbsrc + n] : 0.f;
    }
    __syncthreads();
#pragma unroll
    for (int i = 0; i < 4; i++) {
        int n = n0 + ty + i * 8, k = k0 + tx;
        float v = t[tx][ty + i * 8];
        f16 h = __float2half(v);
        size_t o = (size_t)n * ldbt + kOff + k;
        BtH[o] = h;
        BtL[o] = __float2half(v - __half2float(h));
    }
}
__global__ void convB1_kernel(const float* __restrict__ B, int Ksrc, int Nsrc, int ldbsrc,
                              f16* __restrict__ Bt, int ldbt, int kOff)
{
    __shared__ float t[32][33];
    int k0 = blockIdx.x * 32, n0 = blockIdx.y * 32;
    int tx = threadIdx.x, ty = threadIdx.y;
#pragma unroll
    for (int i = 0; i < 4; i++) {
        int k = k0 + ty + i * 8, n = n0 + tx;
        t[ty + i * 8][tx] = (k < Ksrc && n < Nsrc) ? B[(size_t)k * ldbsrc + n] : 0.f;
    }
    __syncthreads();
#pragma unroll
    for (int i = 0; i < 4; i++) {
        int n = n0 + ty + i * 8, k = k0 + tx;
        Bt[(size_t)n * ldbt + kOff + k] = __float2half(t[tx][ty + i * 8]);
    }
}

// ============================ SIMT SGEMM (Weff only) ============================
#define BM 128
#define BN 128
#define BK 8
__global__ __launch_bounds__(256, 2)
void sgemm_kernel(const float* __restrict__ A, const float* __restrict__ B,
                  float* __restrict__ C, const float* __restrict__ bias,
                  int M, int N, int K, int lda, int ldb, int ldc, int flags, int kChunk)
{
    __shared__ float As[BK][BM];
    __shared__ float Bs[BK][BN];
    const int tid = threadIdx.x;
    const int tx = tid & 15, ty = tid >> 4;
    const int rowBase = blockIdx.y * BM, colBase = blockIdx.x * BN;
    const int kStart = blockIdx.z * kChunk;
    const int kEnd = min(kStart + kChunk, K);
    float acc[8][8];
#pragma unroll
    for (int i = 0; i < 8; i++)
#pragma unroll
        for (int j = 0; j < 8; j++) acc[i][j] = 0.f;
    const int aRow = tid >> 1, aCol = (tid & 1) * 4, gARow = rowBase + aRow;
    const int bRow = tid >> 5, bCol = (tid & 31) * 4, gBCol = colBase + bCol;
    for (int k0 = kStart; k0 < kEnd; k0 += BK) {
        float4 av = make_float4(0.f, 0.f, 0.f, 0.f);
        if (gARow < M) av = *reinterpret_cast<const float4*>(A + (size_t)gARow * lda + k0 + aCol);
        As[aCol + 0][aRow] = av.x; As[aCol + 1][aRow] = av.y;
        As[aCol + 2][aRow] = av.z; As[aCol + 3][aRow] = av.w;
        float4 bv = make_float4(0.f, 0.f, 0.f, 0.f);
        if (gBCol < N) bv = *reinterpret_cast<const float4*>(B + (size_t)(k0 + bRow) * ldb + gBCol);
        *reinterpret_cast<float4*>(&Bs[bRow][bCol]) = bv;
        __syncthreads();
#pragma unroll
        for (int kk = 0; kk < BK; kk++) {
            float4 a0 = *reinterpret_cast<const float4*>(&As[kk][ty * 8]);
            float4 a1 = *reinterpret_cast<const float4*>(&As[kk][ty * 8 + 4]);
            float4 b0 = *reinterpret_cast<const float4*>(&Bs[kk][tx * 8]);
            float4 b1 = *reinterpret_cast<const float4*>(&Bs[kk][tx * 8 + 4]);
            float a[8] = {a0.x, a0.y, a0.z, a0.w, a1.x, a1.y, a1.z, a1.w};
            float b[8] = {b0.x, b0.y, b0.z, b0.w, b1.x, b1.y, b1.z, b1.w};
#pragma unroll
            for (int i = 0; i < 8; i++)
#pragma unroll
                for (int j = 0; j < 8; j++) acc[i][j] = fmaf(a[i], b[j], acc[i][j]);
        }
        __syncthreads();
    }
#pragma unroll
    for (int i = 0; i < 8; i++) {
        int row = rowBase + ty * 8 + i;
        if (row >= M) continue;
#pragma unroll
        for (int j = 0; j < 8; j++) {
            int col = colBase + tx * 8 + j;
            if (col >= N) continue;
            float v = acc[i][j];
            size_t off = (size_t)row * ldc + col;
            if (flags & 4) atomicAdd(&C[off], v);
            else { if (bias) v += bias[col]; C[off] = v; }
        }
    }
}

// ============================ small helpers ============================
__global__ void zero_weff_kernel()
{
    int i = blockIdx.x * 256 + threadIdx.x;
    if (i < 400 * 400) g_Weff[i] = 0.f;
}
__global__ void beff_kernel(const float* __restrict__ bv, const float* __restrict__ Wo,
                            const float* __restrict__ bo)
{
    int d = blockIdx.x * 256 + threadIdx.x;
    if (d >= 400) return;
    float acc = bo[d];
    for (int j = 0; j < 6400; j++) acc = fmaf(bv[j], Wo[(size_t)j * 400 + d], acc);
    g_beff[d] = acc;
}
__global__ void build_xeP(const float* __restrict__ x)
{
    int idx = blockIdx.x * 256 + threadIdx.x;
    if (idx >= 16384 * 416) return;
    int r = idx / 416, k = idx - r * 416;
    float v = (k < 400 && r < 16383) ? x[(size_t)(r + 1) * 1200 + 800 + k] : 0.f;
    g_xeP[idx] = __float2half(v);
}
__global__ void build_flat_f16(const float* __restrict__ x)
{
    int idx = blockIdx.x * 256 + threadIdx.x;
    const int total = 16384 * 1200;
    float v; size_t dst;
    if (idx < total) {
        int b = idx / 1200, c = idx - b * 1200;
        v = x[idx]; dst = (size_t)b * 1600 + c;
    } else if (idx < total + 400) {
        int d = idx - total;
        v = x[800 + d]; dst = 1200 + d;
    } else return;
    g_flatA[dst] = __float2half(v);
}
__global__ void pad_x1_kernel()
{
    int i = blockIdx.x * 256 + threadIdx.x;
    if (i >= 16384 * 48) return;
    int b = i / 48, c = 3600 + i % 48;
    g_x1A[(size_t)b * 3648 + c] = __float2half(0.f);
}

__device__ __forceinline__ float blockReduceSum(float v, float* sh)
{
#pragma unroll
    for (int o = 16; o > 0; o >>= 1) v += __shfl_xor_sync(0xffffffffu, v, o);
    int lane = threadIdx.x & 31, warp = threadIdx.x >> 5;
    if (lane == 0) sh[warp] = v;
    __syncthreads();
    if (warp == 0) {
        float r = (lane < 8) ? sh[lane] : 0.f;
#pragma unroll
        for (int o = 4; o > 0; o >>= 1) r += __shfl_xor_sync(0xffffffffu, r, o);
        if (lane == 0) sh[0] = r;
    }
    __syncthreads();
    float r = sh[0];
    __syncthreads();
    return r;
}

__global__ __launch_bounds__(256)
void frontend_kernel(const float* __restrict__ x,
                     const float* __restrict__ ln1g, const float* __restrict__ ln1b,
                     const float* __restrict__ w1,  const float* __restrict__ fb1,
                     const float* __restrict__ w2,  const float* __restrict__ fb2,
                     const float* __restrict__ ln2g, const float* __restrict__ ln2b)
{
    int b = blockIdx.x;
    const float* xe = x + (size_t)(b + 1) * 1200 + 800;
    const float* at = g_attn + (size_t)b * 400;
    __shared__ float red[32];
    int t = threadIdx.x;
    float sv[2], o1[2], s2v[2];
    int dIdx[2], cnt = 0;
    float sum = 0.f, sq = 0.f;
    for (int d = t; d < 400; d += 256) {
        float v = xe[d] + at[d];
        sv[cnt] = v; dIdx[cnt] = d; cnt++;
        sum += v; sq += v * v;
    }
    sum = blockReduceSum(sum, red);
    sq  = blockReduceSum(sq, red);
    float mean = sum * (1.f / 400.f);
    float var  = sq * (1.f / 400.f) - mean * mean;
    float rstd = rsqrtf(var + 1e-6f);
    float t0 = 0.f, t1 = 0.f;
    for (int i = 0; i < cnt; i++) {
        int d = dIdx[i];
        float o = (sv[i] - mean) * rstd * ln1g[d] + ln1b[d];
        o1[i] = o;
        t0 = fmaf(o, w1[2 * d], t0);
        t1 = fmaf(o, w1[2 * d + 1], t1);
    }
    t0 = blockReduceSum(t0, red);
    t1 = blockReduceSum(t1, red);
    t0 = fmaxf(t0 + fb1[0], 0.f);
    t1 = fmaxf(t1 + fb1[1], 0.f);
    sum = 0.f; sq = 0.f;
    for (int i = 0; i < cnt; i++) {
        int d = dIdx[i];
        float v = o1[i] + t0 * w2[d] + t1 * w2[400 + d] + fb2[d];
        s2v[i] = v; sum += v; sq += v * v;
    }
    sum = blockReduceSum(sum, red);
    sq  = blockReduceSum(sq, red);
    mean = sum * (1.f / 400.f);
    var  = sq * (1.f / 400.f) - mean * mean;
    rstd = rsqrtf(var + 1e-6f);
    size_t base = (size_t)(b + 1) * 1600 + 1200;
    for (int i = 0; i < cnt; i++) {
        int d = dIdx[i];
        g_flatA[base + d] = __float2half((s2v[i] - mean) * rstd * ln2g[d] + ln2b[d]);
    }
}

// Fused GRU elementwise: both directions in one launch, fast MUFU math.
__device__ __forceinline__ float fast_sigmoid(float x)
{
    return __frcp_rn(1.f + __expf(-x));
}
__global__ void gru_elem2_kernel(const float* __restrict__ BrowF, const float* __restrict__ BrowB)
{
    int idx = blockIdx.x * 256 + threadIdx.x;
    if (idx >= 16384 * 1800) return;
    int b = idx / 1800, j = idx - b * 1800;
    // forward (g_G -> x1[:, j])
    {
        const f16* g = g_G + (size_t)b * 5504;
        float z = fast_sigmoid(__half2float(g[j]) + BrowF[j]);
        float r = fast_sigmoid(__half2float(g[1800 + j]) + BrowF[1800 + j]);
        float hv = __half2float(g[3600 + j]) + r * BrowF[3600 + j];
        float hh = (hv > 0.f) ? hv : (__expf(hv) - 1.f);
        g_x1A[(size_t)b * 3648 + j] = __float2half((1.f - z) * hh);
    }
    // backward (g_G2 -> x1[:, 1800 + j])
    {
        const f16* g = g_G2 + (size_t)b * 5504;
        float z = fast_sigmoid(__half2float(g[j]) + BrowB[j]);
        float r = fast_sigmoid(__half2float(g[1800 + j]) + BrowB[1800 + j]);
        float hv = __half2float(g[3600 + j]) + r * BrowB[3600 + j];
        float hh = (hv > 0.f) ? hv : (__expf(hv) - 1.f);
        g_x1A[(size_t)b * 3648 + 1800 + j] = __float2half((1.f - z) * hh);
    }
}

// ============================ host ============================
#define SM_T2 (NSTAGE * 3 * TILE_B)   // 92160
#define SM_T1 (NSTAGE * 2 * TILE_B)   // 61440

extern "C" void kernel_launch(void* const* d_in, const int* in_sizes, int n_in,
                              void* d_out, int out_size)
{
    (void)n_in; (void)out_size;
    const float* x  = (const float*)d_in[0];
    const float* Wv = (const float*)d_in[5];
    const float* bv = (const float*)d_in[6];
    const float* Wo = (const float*)d_in[7];
    const float* bo = (const float*)d_in[8];

    bool sigOrder = (in_sizes[10] == 400);
    const float *ln1g, *ln1b, *w1, *fb1, *w2, *fb2, *ln2g, *ln2b;
    const float *gfk, *gfb, *gbk, *gbb, *d2w, *d2b, *d4w, *d4b, *ow, *ob;
    if (sigOrder) {
        ln1g = (const float*)d_in[9];  ln1b = (const float*)d_in[10];
        w1   = (const float*)d_in[11]; fb1  = (const float*)d_in[12];
        w2   = (const float*)d_in[13]; fb2  = (const float*)d_in[14];
        ln2g = (const float*)d_in[15]; ln2b = (const float*)d_in[16];
        gfk  = (const float*)d_in[17]; gfb  = (const float*)d_in[19];
        gbk  = (const float*)d_in[20]; gbb  = (const float*)d_in[22];
        d2w  = (const float*)d_in[23]; d2b  = (const float*)d_in[24];
        d4w  = (const float*)d_in[25]; d4b  = (const float*)d_in[26];
        ow   = (const float*)d_in[27]; ob   = (const float*)d_in[28];
    } else {
        ln1b = (const float*)d_in[9];
        w1   = (const float*)d_in[10]; fb1  = (const float*)d_in[11];
        w2   = (const float*)d_in[12]; fb2  = (const float*)d_in[13];
        ln2b = (const float*)d_in[14];
        gfk  = (const float*)d_in[15]; gfb  = (const float*)d_in[17];
        gbk  = (const float*)d_in[18]; gbb  = (const float*)d_in[20];
        d2w  = (const float*)d_in[21]; d2b  = (const float*)d_in[22];
        d4w  = (const float*)d_in[23]; d4b  = (const float*)d_in[24];
        ow   = (const float*)d_in[25]; ob   = (const float*)d_in[26];
        ln1g = (const float*)d_in[27]; ln2g = (const float*)d_in[28];
    }

    float *pWeff, *pbeff, *pattn;
    f16 *pG, *pG2, *pxeP, *pWeH, *pWeL, *pflatA, *px1A, *px3A, *px5A;
    f16 *pBgf, *pBgb, *pBd2, *pBd4, *pBo;
    cudaGetSymbolAddress((void**)&pWeff, g_Weff);
    cudaGetSymbolAddress((void**)&pbeff, g_beff);
    cudaGetSymbolAddress((void**)&pattn, g_attn);
    cudaGetSymbolAddress((void**)&pG, g_G);
    cudaGetSymbolAddress((void**)&pG2, g_G2);
    cudaGetSymbolAddress((void**)&pxeP, g_xeP);
    cudaGetSymbolAddress((void**)&pWeH, g_WeffH);
    cudaGetSymbolAddress((void**)&pWeL, g_WeffL);
    cudaGetSymbolAddress((void**)&pflatA, g_flatA);
    cudaGetSymbolAddress((void**)&px1A, g_x1A);
    cudaGetSymbolAddress((void**)&px3A, g_x3A);
    cudaGetSymbolAddress((void**)&px5A, g_x5A);
    cudaGetSymbolAddress((void**)&pBgf, g_Bgf);
    cudaGetSymbolAddress((void**)&pBgb, g_Bgb);
    cudaGetSymbolAddress((void**)&pBd2, g_Bd2);
    cudaGetSymbolAddress((void**)&pBd4, g_Bd4);
    cudaGetSymbolAddress((void**)&pBo, g_Bo);
    float* out = (float*)d_out;

    cudaFuncSetAttribute(hmma_gemm<1, 1>, cudaFuncAttributeMaxDynamicSharedMemorySize, SM_T1);
    cudaFuncSetAttribute(hmma_gemm<2, 1>, cudaFuncAttributeMaxDynamicSharedMemorySize, SM_T1);
    cudaFuncSetAttribute(hmma_gemm<2, 2>, cudaFuncAttributeMaxDynamicSharedMemorySize, SM_T2);
    cudaFuncSetAttribute(hmma_gemm<3, 1>, cudaFuncAttributeMaxDynamicSharedMemorySize, SM_T1);

    // --- front-end ---
    zero_weff_kernel<<<(400 * 400 + 255) / 256, 256>>>();
    { dim3 g(4, 4, 8); sgemm_kernel<<<g, 256>>>(Wv, Wo, pWeff, nullptr, 400, 400, 6400, 6400, 400, 400, 4, 800); }
    beff_kernel<<<2, 256>>>(bv, Wo, bo);
    { dim3 g(13, 16); convB_kernel<<<g, dim3(32, 8)>>>(pWeff, 400, 400, 400, pWeH, pWeL, 416, 0); }
    build_xeP<<<(16384 * 416 + 255) / 256, 256>>>(x);
    // attn = xeP @ WeffT^T + beff (tensor, 2-term, EPI2)
    { dim3 g(4, 128);
      hmma_gemm<2, 2><<<g, 256, SM_T2>>>(pxeP, pxeP, pxeP, 416, 416, 416, 416, 416, 416,
                                         pWeH, pWeL, 416, pattn, 400, pbeff, 400, nullptr, 0, 400); }
    build_flat_f16<<<(16384 * 1200 + 400 + 255) / 256, 256>>>(x);
    frontend_kernel<<<16383, 256>>>(x, ln1g, ln1b, w1, fb1, w2, fb2, ln2g, ln2b);

    // --- weight conversion ---
    { dim3 g(50, 172);  convB1_kernel<<<g, dim3(32, 8)>>>(gfk, 1600, 5400, 5400, pBgf, 1600, 0); }
    { dim3 g(50, 172);  convB1_kernel<<<g, dim3(32, 8)>>>(gbk, 1600, 5400, 5400, pBgb, 1600, 0); }
    { dim3 g(114, 60);  convB1_kernel<<<g, dim3(32, 8)>>>(d2w, 3600, 1800, 1800, pBd2, 3648, 0); }
    { dim3 g(60, 60);   convB1_kernel<<<g, dim3(32, 8)>>>(d4w, 1800, 1800, 1800, pBd4, 1920, 0); }
    { dim3 g(114, 8);   convB1_kernel<<<g, dim3(32, 8)>>>(ow,              3600, 140, 140, pBo, 7488, 0); }
    { dim3 g(60, 8);    convB1_kernel<<<g, dim3(32, 8)>>>(ow + 3600 * 140, 1800, 140, 140, pBo, 7488, 3648); }
    { dim3 g(60, 8);    convB1_kernel<<<g, dim3(32, 8)>>>(ow + 5400 * 140, 1800, 140, 140, pBo, 7488, 5568); }
    pad_x1_kernel<<<(16384 * 48 + 255) / 256, 256>>>();

    // --- tensor-core GEMMs ---
    // GRU fwd + bwd preacts (1-term, EPI3), then fused elementwise
    { dim3 g(43, 128);
      hmma_gemm<3, 1><<<g, 256, SM_T1>>>(pflatA, pflatA, pflatA, 1600, 1600, 1600, 1600, 1600, 1600,
                                         pBgf, nullptr, 1600, nullptr, 0, gfb, 5400, pG, 5504, 5504); }
    { dim3 g(43, 128);
      hmma_gemm<3, 1><<<g, 256, SM_T1>>>(pflatA, pflatA, pflatA, 1600, 1600, 1600, 1600, 1600, 1600,
                                         pBgb, nullptr, 1600, nullptr, 0, gbb, 5400, pG2, 5504, 5504); }
    gru_elem2_kernel<<<(16384 * 1800 + 255) / 256, 256>>>(gfb + 5400, gbb + 5400);
    // x3 = elu(x1 @ d2w + b), 1-term
    { dim3 g(15, 128);
      hmma_gemm<1, 1><<<g, 256, SM_T1>>>(px1A, px1A, px1A, 3648, 3648, 3648, 3648, 3648, 3648,
                                         pBd2, nullptr, 3648, nullptr, 0, d2b, 1800, px3A, 1920, 1920); }
    // x5 = elu(x3 @ d4w + b), 1-term
    { dim3 g(15, 128);
      hmma_gemm<1, 1><<<g, 256, SM_T1>>>(px3A, px3A, px3A, 1920, 1920, 1920, 1920, 1920, 1920,
                                         pBd4, nullptr, 1920, nullptr, 0, d4b, 1800, px5A, 1920, 1920); }
    // out = [x1|x3|x5] @ Bo^T + ob, 1-term
    { dim3 g(2, 128);
      hmma_gemm<2, 1><<<g, 256, SM_T1>>>(px1A, px3A, px5A, 3648, 1920, 1920, 3648, 5568, 7488,
                                         pBo, nullptr, 7488, out, 140, ob, 140, nullptr, 0, 140); }
}